// round 8
// baseline (speedup 1.0000x reference)
#include <cuda_runtime.h>
#include <cuda_fp16.h>
#include <cstdint>

// Problem constants
#define BATCH 2
#define SEQ   2048
#define DIM   1024
#define HEADS 16
#define DHEAD 64

typedef __half f16;

// Scratch (device globals — no allocations allowed)
__device__ f16 g_xh [(size_t)BATCH * SEQ * DIM];
__device__ f16 g_wih[(size_t)3 * DIM * DIM];
__device__ f16 g_wil[(size_t)3 * DIM * DIM];
__device__ f16 g_woh[(size_t)DIM * DIM];
__device__ f16 g_wol[(size_t)DIM * DIM];
__device__ f16 g_qkvh[(size_t)BATCH * SEQ * 3 * DIM];
__device__ f16 g_qkvl[(size_t)BATCH * SEQ * 3 * DIM];
__device__ f16 g_ah [(size_t)BATCH * SEQ * DIM];

// ---------------------------------------------------------------------------
// helpers
// ---------------------------------------------------------------------------
__device__ __forceinline__ uint32_t smem_u32(const void* p) {
    uint32_t a;
    asm("{ .reg .u64 t; cvta.to.shared.u64 t, %1; cvt.u32.u64 %0, t; }" : "=r"(a) : "l"(p));
    return a;
}

__device__ __forceinline__ void ldmatrix_x4(uint32_t* r, uint32_t addr) {
    asm volatile("ldmatrix.sync.aligned.m8n8.x4.shared.b16 {%0,%1,%2,%3}, [%4];"
                 : "=r"(r[0]), "=r"(r[1]), "=r"(r[2]), "=r"(r[3]) : "r"(addr));
}

__device__ __forceinline__ void ldmatrix_x4_trans(uint32_t* r, uint32_t addr) {
    asm volatile("ldmatrix.sync.aligned.m8n8.x4.trans.shared.b16 {%0,%1,%2,%3}, [%4];"
                 : "=r"(r[0]), "=r"(r[1]), "=r"(r[2]), "=r"(r[3]) : "r"(addr));
}

__device__ __forceinline__ void mma_f16(float* c, const uint32_t* a, const uint32_t* b) {
    asm volatile(
        "mma.sync.aligned.m16n8k16.row.col.f32.f16.f16.f32 "
        "{%0,%1,%2,%3}, {%4,%5,%6,%7}, {%8,%9}, {%0,%1,%2,%3};"
        : "+f"(c[0]), "+f"(c[1]), "+f"(c[2]), "+f"(c[3])
        : "r"(a[0]), "r"(a[1]), "r"(a[2]), "r"(a[3]), "r"(b[0]), "r"(b[1]));
}

__device__ __forceinline__ uint32_t pack_f16(float a, float b) {
    __half2 t = __floats2half2_rn(a, b);
    return *(uint32_t*)&t;
}

__device__ __forceinline__ void cp16(uint32_t dst, const void* src) {
    asm volatile("cp.async.cg.shared.global [%0], [%1], 16;" :: "r"(dst), "l"(src));
}
#define CP_COMMIT() asm volatile("cp.async.commit_group;" ::: "memory")
#define CP_WAIT1()  asm volatile("cp.async.wait_group 1;" ::: "memory")
#define CP_WAIT0()  asm volatile("cp.async.wait_group 0;" ::: "memory")

// ---------------------------------------------------------------------------
// fp32 -> fp16 converters
// ---------------------------------------------------------------------------
__global__ void cvt_hi(const float4* __restrict__ in, uint2* __restrict__ hi, int n4)
{
    int i = blockIdx.x * blockDim.x + threadIdx.x;
    if (i >= n4) return;
    float4 f = in[i];
    hi[i] = make_uint2(pack_f16(f.x, f.y), pack_f16(f.z, f.w));
}

__global__ void cvt_hilo(const float4* __restrict__ in,
                         uint2* __restrict__ hi, uint2* __restrict__ lo, int n4)
{
    int i = blockIdx.x * blockDim.x + threadIdx.x;
    if (i >= n4) return;
    float4 f = in[i];
    float v[4] = {f.x, f.y, f.z, f.w};
    float h[4];
#pragma unroll
    for (int j = 0; j < 4; j++) h[j] = __half2float(__float2half_rn(v[j]));
    hi[i] = make_uint2(pack_f16(h[0], h[1]), pack_f16(h[2], h[3]));
    lo[i] = make_uint2(pack_f16(v[0] - h[0], v[1] - h[1]),
                       pack_f16(v[2] - h[2], v[3] - h[3]));
}

// ---------------------------------------------------------------------------
// GEMM-256: 256x128 CTA tile, fp16x2 (C = Ah*(Bh+Bl) + bias), 512 threads.
// 16 warps: warpM = wid&3 (4x64 rows), warpN = wid>>2 (4x32 cols).
// BK=32, 3-stage cp.async. Stage = [Ah 20480 | Bh 10240 | Bl 10240] = 40960.
// Optional Q-scale: columns < qcols get *0.125 after bias (exact pow2).
// ---------------------------------------------------------------------------
#define G2TILE_A 20480
#define G2TILE_B 10240
#define G2STG    40960
#define GEMM2_SMEM (3 * G2STG)    // 122880

__global__ __launch_bounds__(512, 1)
void gemm2_f16x2(int M, int N, int K,
                 const f16* __restrict__ Ah,
                 const f16* __restrict__ Bh, const f16* __restrict__ Bl,
                 const float* __restrict__ bias, int qcols,
                 f16* __restrict__ Ch, f16* __restrict__ Cl)
{
    extern __shared__ char smem[];
    const uint32_t sb = smem_u32(smem);
    const int tid = threadIdx.x, wid = tid >> 5, lane = tid & 31;
    const int bx = blockIdx.x, by = blockIdx.y;
    const int warpM = wid & 3, warpN = wid >> 2;

    // cp.async mapping: A all threads (256 rows x 2 thr), B hi (tid<256) / lo
    const int ar = tid >> 1;
    const int acb = (tid & 1) * 2;
    const f16* pA = Ah + (size_t)(by * 256 + ar) * K;
    const uint32_t adst = sb + (uint32_t)(ar * 80 + acb * 16);
    const int br = (tid & 255) >> 1;
    const f16* pB = ((tid < 256) ? Bh : Bl) + (size_t)(bx * 128 + br) * K;
    const uint32_t bdst = sb + (uint32_t)(G2TILE_A + (tid < 256 ? 0 : G2TILE_B)
                                          + br * 80 + acb * 16);

    float acc[4][4][4];
#pragma unroll
    for (int i = 0; i < 4; i++)
#pragma unroll
        for (int j = 0; j < 4; j++)
#pragma unroll
            for (int v = 0; v < 4; v++) acc[i][j][v] = 0.f;

    const int KC = K >> 5;

    auto issue = [&](int kt, int s) {
        const int k0 = kt * 32 + acb * 8;
        const uint32_t sa = adst + (uint32_t)(s * G2STG);
        const uint32_t sbm = bdst + (uint32_t)(s * G2STG);
        cp16(sa,       pA + k0);
        cp16(sa + 16,  pA + k0 + 8);
        cp16(sbm,      pB + k0);
        cp16(sbm + 16, pB + k0 + 8);
        CP_COMMIT();
    };

    issue(0, 0);
    issue(1, 1);

    const int aRow = warpM * 64 + ((lane >> 3) & 1) * 8 + (lane & 7);
    const int aColHalf = (lane >> 4) * 16;
    const int bRow = warpN * 32 + (lane >> 4) * 8 + (lane & 7);
    const int bColHalf = ((lane >> 3) & 1) * 16;

    for (int kt = 0; kt < KC; kt++) {
        CP_WAIT1();
        __syncthreads();
        if (kt + 2 < KC) issue(kt + 2, (kt + 2) % 3);
        else             CP_COMMIT();

        const uint32_t sA  = sb + (uint32_t)((kt % 3) * G2STG);
        const uint32_t sBh = sA + G2TILE_A;
        const uint32_t sBl = sBh + G2TILE_B;

#pragma unroll
        for (int ks = 0; ks < 2; ks++) {
            uint32_t ah[4][4], bh[4][2], bl[4][2];
            const uint32_t acol = (uint32_t)(ks * 32 + aColHalf);
            const uint32_t bcol = (uint32_t)(ks * 32 + bColHalf);
#pragma unroll
            for (int mt = 0; mt < 4; mt++) {
                uint32_t off = (uint32_t)((aRow + mt * 16) * 80) + acol;
                ldmatrix_x4(ah[mt], sA + off);
            }
#pragma unroll
            for (int pr = 0; pr < 2; pr++) {
                uint32_t off = (uint32_t)((bRow + pr * 16) * 80) + bcol;
                uint32_t r0[4], r1[4];
                ldmatrix_x4(r0, sBh + off);
                ldmatrix_x4(r1, sBl + off);
                bh[pr * 2 + 0][0] = r0[0]; bh[pr * 2 + 0][1] = r0[1];
                bh[pr * 2 + 1][0] = r0[2]; bh[pr * 2 + 1][1] = r0[3];
                bl[pr * 2 + 0][0] = r1[0]; bl[pr * 2 + 0][1] = r1[1];
                bl[pr * 2 + 1][0] = r1[2]; bl[pr * 2 + 1][1] = r1[3];
            }
#pragma unroll
            for (int mt = 0; mt < 4; mt++)
#pragma unroll
                for (int nt = 0; nt < 4; nt++) {
                    mma_f16(acc[mt][nt], ah[mt], bh[nt]);
                    mma_f16(acc[mt][nt], ah[mt], bl[nt]);
                }
        }
    }

    // epilogue -> fp16 hi/lo, Q-columns scaled by 0.125
    const int crow = by * 256 + warpM * 64 + (lane >> 2);
    const int ccol = bx * 128 + warpN * 32 + (lane & 3) * 2;
#pragma unroll
    for (int nt = 0; nt < 4; nt++) {
        const int col = ccol + nt * 8;
        const float s = (col < qcols) ? 0.125f : 1.0f;
        const float b0 = bias[col], b1 = bias[col + 1];
#pragma unroll
        for (int mt = 0; mt < 4; mt++) {
            const int r0 = crow + mt * 16;
            const float v00 = (acc[mt][nt][0] + b0) * s, v01 = (acc[mt][nt][1] + b1) * s;
            const float v10 = (acc[mt][nt][2] + b0) * s, v11 = (acc[mt][nt][3] + b1) * s;
            float h00 = __half2float(__float2half_rn(v00));
            float h01 = __half2float(__float2half_rn(v01));
            float h10 = __half2float(__float2half_rn(v10));
            float h11 = __half2float(__float2half_rn(v11));
            *(uint32_t*)(Ch + (size_t)r0 * N + col)       = pack_f16(h00, h01);
            *(uint32_t*)(Cl + (size_t)r0 * N + col)       = pack_f16(v00 - h00, v01 - h01);
            *(uint32_t*)(Ch + (size_t)(r0 + 8) * N + col) = pack_f16(h10, h11);
            *(uint32_t*)(Cl + (size_t)(r0 + 8) * N + col) = pack_f16(v10 - h10, v11 - h11);
        }
    }
}

// ---------------------------------------------------------------------------
// GEMM-128 (proj): unchanged Round-7 structure, fp32 output.
// ---------------------------------------------------------------------------
#define GTILE 10240
#define GSTG  (3 * GTILE)
#define GEMM_SMEM (3 * GSTG)

__global__ __launch_bounds__(256, 2)
void gemm_f16x2(int M, int N, int K,
                const f16* __restrict__ Ah,
                const f16* __restrict__ Bh, const f16* __restrict__ Bl,
                const float* __restrict__ bias,
                float* __restrict__ C)
{
    extern __shared__ char smem[];
    const uint32_t sb = smem_u32(smem);
    const int tid = threadIdx.x, wid = tid >> 5, lane = tid & 31;
    const int bx = blockIdx.x, by = blockIdx.y;
    const int warpM = wid & 1, warpN = wid >> 1;

    const int r = tid >> 1;
    const int cb = (tid & 1) * 2;
    const f16* pAh = Ah + (size_t)(by * 128 + r) * K;
    const f16* pBh = Bh + (size_t)(bx * 128 + r) * K;
    const f16* pBl = Bl + (size_t)(bx * 128 + r) * K;
    const uint32_t sdst = sb + (uint32_t)(r * 80 + cb * 16);

    float acc[4][4][4];
#pragma unroll
    for (int i = 0; i < 4; i++)
#pragma unroll
        for (int j = 0; j < 4; j++)
#pragma unroll
            for (int v = 0; v < 4; v++) acc[i][j][v] = 0.f;

    const int KC = K >> 5;

    auto issue = [&](int kt, int s) {
        const int k0 = kt * 32 + cb * 8;
        const uint32_t d = sdst + (uint32_t)(s * GSTG);
        cp16(d,                  pAh + k0);
        cp16(d + 16,             pAh + k0 + 8);
        cp16(d + GTILE,          pBh + k0);
        cp16(d + GTILE + 16,     pBh + k0 + 8);
        cp16(d + 2 * GTILE,      pBl + k0);
        cp16(d + 2 * GTILE + 16, pBl + k0 + 8);
        CP_COMMIT();
    };

    issue(0, 0);
    issue(1, 1);

    const int aRow = warpM * 64 + ((lane >> 3) & 1) * 8 + (lane & 7);
    const int aColHalf = (lane >> 4) * 16;
    const int bRow = warpN * 32 + (lane >> 4) * 8 + (lane & 7);
    const int bColHalf = ((lane >> 3) & 1) * 16;

    for (int kt = 0; kt < KC; kt++) {
        CP_WAIT1();
        __syncthreads();
        if (kt + 2 < KC) issue(kt + 2, (kt + 2) % 3);
        else             CP_COMMIT();

        const uint32_t sAh = sb + (uint32_t)((kt % 3) * GSTG);
        const uint32_t sBh = sAh + GTILE;
        const uint32_t sBl = sAh + 2 * GTILE;

#pragma unroll
        for (int ks = 0; ks < 2; ks++) {
            uint32_t ah[4][4], bh[4][2], bl[4][2];
            const uint32_t acol = (uint32_t)(ks * 32 + aColHalf);
            const uint32_t bcol = (uint32_t)(ks * 32 + bColHalf);
#pragma unroll
            for (int mt = 0; mt < 4; mt++) {
                uint32_t off = (uint32_t)((aRow + mt * 16) * 80) + acol;
                ldmatrix_x4(ah[mt], sAh + off);
            }
#pragma unroll
            for (int pr = 0; pr < 2; pr++) {
                uint32_t off = (uint32_t)((bRow + pr * 16) * 80) + bcol;
                uint32_t r0[4], r1[4];
                ldmatrix_x4(r0, sBh + off);
                ldmatrix_x4(r1, sBl + off);
                bh[pr * 2 + 0][0] = r0[0]; bh[pr * 2 + 0][1] = r0[1];
                bh[pr * 2 + 1][0] = r0[2]; bh[pr * 2 + 1][1] = r0[3];
                bl[pr * 2 + 0][0] = r1[0]; bl[pr * 2 + 0][1] = r1[1];
                bl[pr * 2 + 1][0] = r1[2]; bl[pr * 2 + 1][1] = r1[3];
            }
#pragma unroll
            for (int mt = 0; mt < 4; mt++)
#pragma unroll
                for (int nt = 0; nt < 4; nt++) {
                    mma_f16(acc[mt][nt], ah[mt], bh[nt]);
                    mma_f16(acc[mt][nt], ah[mt], bl[nt]);
                }
        }
    }

    const int crow = by * 128 + warpM * 64 + (lane >> 2);
    const int ccol = bx * 128 + warpN * 32 + (lane & 3) * 2;
#pragma unroll
    for (int nt = 0; nt < 4; nt++) {
        const int col = ccol + nt * 8;
        const float b0 = bias[col], b1 = bias[col + 1];
#pragma unroll
        for (int mt = 0; mt < 4; mt++) {
            const int r0 = crow + mt * 16;
            *(float2*)(C + (size_t)r0 * N + col) =
                make_float2(acc[mt][nt][0] + b0, acc[mt][nt][1] + b1);
            *(float2*)(C + (size_t)(r0 + 8) * N + col) =
                make_float2(acc[mt][nt][2] + b0, acc[mt][nt][3] + b1);
        }
    }
}

// ---------------------------------------------------------------------------
// Flash attention, mma.sync fp16x2, causal. Q pre-scaled by 0.125 upstream.
// 2-stage cp.async pipeline, 2 CTAs/SM target.
// Stage (36864B) = [Kh 9216 | Kl 9216 | Vh 9216 | Vl 9216], rows 144B.
// ---------------------------------------------------------------------------
#define ASTR 144
#define KV_T 9216
#define STG_A 36864
#define ATT_SMEM (2 * STG_A)       // 73728

__global__ __launch_bounds__(256, 2)
void attn_mma(const f16* __restrict__ qkvh, const f16* __restrict__ qkvl,
              f16* __restrict__ oh, const int* __restrict__ maskp)
{
    extern __shared__ char sm[];
    const uint32_t sb = smem_u32(sm);
    const int tid = threadIdx.x, wid = tid >> 5, lane = tid & 31;
    const int qt = gridDim.x - 1 - blockIdx.x;     // long CTAs first
    const int bh = blockIdx.y;
    const int b = bh >> 4, h = bh & 15;
    const int mask = maskp[0];
    const int q0 = qt * 128;

    // ---- stage Qh via cp.async, consume into registers ----
    {
        const int r = tid >> 1, c0 = (tid & 1) * 4;
        const size_t grow = ((size_t)(b * SEQ + q0 + r)) * (3 * DIM) + h * 64 + c0 * 8;
        const uint32_t dh = sb + (uint32_t)(r * ASTR + c0 * 16);
#pragma unroll
        for (int j = 0; j < 4; j++)
            cp16(dh + j * 16, qkvh + grow + j * 8);
        CP_COMMIT();
        CP_WAIT0();
        __syncthreads();
    }

    uint32_t qh[4][4];
#pragma unroll
    for (int j = 0; j < 4; j++) {
        uint32_t addr = sb + (uint32_t)((wid * 16 + (lane & 15)) * ASTR
                       + (j * 16 + ((lane >> 4) & 1) * 8) * 2);
        ldmatrix_x4(qh[j], addr);
    }
    __syncthreads();

    float o[8][4];
#pragma unroll
    for (int t = 0; t < 8; t++)
#pragma unroll
        for (int v = 0; v < 4; v++) o[t][v] = 0.f;
    float m0 = -1e30f, m1 = -1e30f, l0 = 0.f, l1 = 0.f;

    const int nkt_load = mask ? (2 * qt + 2) : (SEQ / 64);
    const int nkt_w    = mask ? (2 * qt + 1 + (wid >= 4 ? 1 : 0)) : (SEQ / 64);

    const int tt = tid & 127;
    const int kr = tt >> 1, kc0 = (tt & 1) * 4;
    const size_t kvcol = h * 64 + (tid < 128 ? DIM : 2 * DIM) + kc0 * 8;
    const uint32_t kvdst = (uint32_t)((tid < 128 ? 0 : 2 * KV_T) + kr * ASTR + kc0 * 16);
    auto issueKV = [&](int kt, int s) {
        const size_t grow = ((size_t)(b * SEQ + kt * 64 + kr)) * (3 * DIM) + kvcol;
        const uint32_t d = sb + (uint32_t)(s * STG_A) + kvdst;
#pragma unroll
        for (int j = 0; j < 4; j++) {
            cp16(d + j * 16,        qkvh + grow + j * 8);
            cp16(d + KV_T + j * 16, qkvl + grow + j * 8);
        }
        CP_COMMIT();
    };

    issueKV(0, 0);

    const uint32_t koff = (uint32_t)(
        (((lane >> 4) << 3) + (lane & 7)) * ASTR + (((lane >> 3) & 1) * 8) * 2);
    const uint32_t voff = (uint32_t)(2 * KV_T +
        ((((lane >> 3) & 1) * 8 + (lane & 7)) * ASTR) + (((lane >> 4) & 1) * 8) * 2);

    for (int kt = 0; kt < nkt_load; kt++) {
        CP_WAIT0();
        __syncthreads();
        if (kt + 1 < nkt_load) issueKV(kt + 1, (kt + 1) & 1);
        if (kt >= nkt_w) continue;

        const uint32_t stg = sb + (uint32_t)((kt & 1) * STG_A);
        const uint32_t kfrag = stg + koff;
        const uint32_t vfrag = stg + voff;

        // ---- scores = Qs*(Kh+Kl) (Q pre-scaled) ----
        float sc[8][4];
#pragma unroll
        for (int t = 0; t < 8; t++)
#pragma unroll
            for (int v = 0; v < 4; v++) sc[t][v] = 0.f;

#pragma unroll
        for (int j = 0; j < 4; j++) {
#pragma unroll
            for (int t = 0; t < 4; t++) {
                uint32_t addr = kfrag + (uint32_t)(t * 16 * ASTR + j * 32);
                uint32_t rh[4], rl[4];
                ldmatrix_x4(rh, addr);
                ldmatrix_x4(rl, addr + KV_T);
                mma_f16(sc[2 * t + 0], qh[j], rh);
                mma_f16(sc[2 * t + 1], qh[j], rh + 2);
                mma_f16(sc[2 * t + 0], qh[j], rl);
                mma_f16(sc[2 * t + 1], qh[j], rl + 2);
            }
        }

        // ---- online softmax ----
        const int row0 = q0 + wid * 16 + (lane >> 2);
        const int row1 = row0 + 8;
        const int cbase = kt * 64 + (lane & 3) * 2;
        const bool needmask = mask && (kt * 64 + 63 > q0 + wid * 16);
        if (needmask) {
#pragma unroll
            for (int t = 0; t < 8; t++) {
                int c0 = cbase + t * 8, c1 = c0 + 1;
                if (c0 > row0) sc[t][0] = -1e30f;
                if (c1 > row0) sc[t][1] = -1e30f;
                if (c0 > row1) sc[t][2] = -1e30f;
                if (c1 > row1) sc[t][3] = -1e30f;
            }
        }
        float mt0 = -1e30f, mt1 = -1e30f;
#pragma unroll
        for (int t = 0; t < 8; t++) {
            mt0 = fmaxf(mt0, fmaxf(sc[t][0], sc[t][1]));
            mt1 = fmaxf(mt1, fmaxf(sc[t][2], sc[t][3]));
        }
        mt0 = fmaxf(mt0, __shfl_xor_sync(0xffffffffu, mt0, 1));
        mt0 = fmaxf(mt0, __shfl_xor_sync(0xffffffffu, mt0, 2));
        mt1 = fmaxf(mt1, __shfl_xor_sync(0xffffffffu, mt1, 1));
        mt1 = fmaxf(mt1, __shfl_xor_sync(0xffffffffu, mt1, 2));
        const float mn0 = fmaxf(m0, mt0), mn1 = fmaxf(m1, mt1);
        const float a0 = __expf(m0 - mn0), a1 = __expf(m1 - mn1);

        uint32_t ph[8][2];
        float s0 = 0.f, s1 = 0.f;
#pragma unroll
        for (int t = 0; t < 8; t++) {
            float p00 = __expf(sc[t][0] - mn0);
            float p01 = __expf(sc[t][1] - mn0);
            float p10 = __expf(sc[t][2] - mn1);
            float p11 = __expf(sc[t][3] - mn1);
            s0 += p00 + p01;
            s1 += p10 + p11;
            ph[t][0] = pack_f16(p00, p01);
            ph[t][1] = pack_f16(p10, p11);
        }
        s0 += __shfl_xor_sync(0xffffffffu, s0, 1);
        s0 += __shfl_xor_sync(0xffffffffu, s0, 2);
        s1 += __shfl_xor_sync(0xffffffffu, s1, 1);
        s1 += __shfl_xor_sync(0xffffffffu, s1, 2);
        m0 = mn0; m1 = mn1;
        l0 = l0 * a0 + s0;
        l1 = l1 * a1 + s1;
#pragma unroll
        for (int t = 0; t < 8; t++) {
            o[t][0] *= a0; o[t][1] *= a0;
            o[t][2] *= a1; o[t][3] *= a1;
        }

        // ---- O += Ph*(Vh+Vl) ----
#pragma unroll
        for (int j = 0; j < 4; j++) {
            uint32_t afh[4] = { ph[2*j][0], ph[2*j][1], ph[2*j+1][0], ph[2*j+1][1] };
#pragma unroll
            for (int t = 0; t < 4; t++) {
                uint32_t addr = vfrag + (uint32_t)(j * 16 * ASTR + t * 32);
                uint32_t rh[4], rl[4];
                ldmatrix_x4_trans(rh, addr);
                ldmatrix_x4_trans(rl, addr + KV_T);
                mma_f16(o[2 * t + 0], afh, rh);
                mma_f16(o[2 * t + 1], afh, rh + 2);
                mma_f16(o[2 * t + 0], afh, rl);
                mma_f16(o[2 * t + 1], afh, rl + 2);
            }
        }
    }

    // ---- write O (fp16 hi — feeds proj as A operand) ----
    const float il0 = 1.0f / l0, il1 = 1.0f / l1;
    const int orow = q0 + wid * 16 + (lane >> 2);
    const size_t obase = ((size_t)b * SEQ + orow) * DIM + h * 64 + (lane & 3) * 2;
#pragma unroll
    for (int t = 0; t < 8; t++) {
        *(uint32_t*)(oh + obase + t * 8)           = pack_f16(o[t][0] * il0, o[t][1] * il0);
        *(uint32_t*)(oh + obase + 8 * DIM + t * 8) = pack_f16(o[t][2] * il1, o[t][3] * il1);
    }
}

// ---------------------------------------------------------------------------
// Launch
// ---------------------------------------------------------------------------
extern "C" void kernel_launch(void* const* d_in, const int* in_sizes, int n_in,
                              void* d_out, int out_size)
{
    const float* x     = (const float*)d_in[0];
    const float* w_in  = (const float*)d_in[1];
    const float* b_in  = (const float*)d_in[2];
    const float* w_out = (const float*)d_in[3];
    const float* b_out = (const float*)d_in[4];
    const int*   mask  = (const int*)d_in[5];
    float* out = (float*)d_out;

    f16 *xh, *wih, *wil, *woh, *wol, *qkvh, *qkvl, *ah;
    cudaGetSymbolAddress((void**)&xh,  g_xh);
    cudaGetSymbolAddress((void**)&wih, g_wih);
    cudaGetSymbolAddress((void**)&wil, g_wil);
    cudaGetSymbolAddress((void**)&woh, g_woh);
    cudaGetSymbolAddress((void**)&wol, g_wol);
    cudaGetSymbolAddress((void**)&qkvh, g_qkvh);
    cudaGetSymbolAddress((void**)&qkvl, g_qkvl);
    cudaGetSymbolAddress((void**)&ah,  g_ah);

    const int M = BATCH * SEQ;      // 4096
    const int K = DIM;              // 1024
    const int N1 = 3 * DIM;         // 3072
    const int N2 = DIM;             // 1024

    cudaFuncSetAttribute(gemm2_f16x2, cudaFuncAttributeMaxDynamicSharedMemorySize, GEMM2_SMEM);
    cudaFuncSetAttribute(gemm_f16x2,  cudaFuncAttributeMaxDynamicSharedMemorySize, GEMM_SMEM);
    cudaFuncSetAttribute(attn_mma,    cudaFuncAttributeMaxDynamicSharedMemorySize, ATT_SMEM);

    // 0) convert inputs (x: hi only; weights: hi+lo)
    {
        int n4x = M * K / 4;
        int n4w = N1 * K / 4;
        int n4o = N2 * K / 4;
        cvt_hi  <<<(n4x + 255) / 256, 256>>>((const float4*)x, (uint2*)xh, n4x);
        cvt_hilo<<<(n4w + 255) / 256, 256>>>((const float4*)w_in, (uint2*)wih, (uint2*)wil, n4w);
        cvt_hilo<<<(n4o + 255) / 256, 256>>>((const float4*)w_out, (uint2*)woh, (uint2*)wol, n4o);
    }
    // 1) QKV projection -> fp16 hi/lo (Q columns pre-scaled by 0.125)
    {
        dim3 grid(N1 / 128, M / 256);
        gemm2_f16x2<<<grid, 512, GEMM2_SMEM>>>(M, N1, K, xh, wih, wil, b_in, DIM,
                                               qkvh, qkvl);
    }
    // 2) causal attention -> fp16 hi
    {
        dim3 grid(SEQ / 128, BATCH * HEADS);
        attn_mma<<<grid, 256, ATT_SMEM>>>(qkvh, qkvl, ah, mask);
    }
    // 3) output projection -> fp32 out
    {
        dim3 grid(N2 / 128, M / 128);
        gemm_f16x2<<<grid, 256, GEMM_SMEM>>>(M, N2, K, ah, woh, wol, b_out, out);
    }
}

// round 9
// speedup vs baseline: 1.2527x; 1.2527x over previous
#include <cuda_runtime.h>
#include <cuda_fp16.h>
#include <cstdint>

// Problem constants
#define BATCH 2
#define SEQ   2048
#define DIM   1024
#define HEADS 16
#define DHEAD 64

typedef __half f16;

// Scratch (device globals — no allocations allowed)
__device__ f16 g_xh [(size_t)BATCH * SEQ * DIM];
__device__ f16 g_wih[(size_t)3 * DIM * DIM];
__device__ f16 g_wil[(size_t)3 * DIM * DIM];
__device__ f16 g_woh[(size_t)DIM * DIM];
__device__ f16 g_wol[(size_t)DIM * DIM];
__device__ f16 g_qkvh[(size_t)BATCH * SEQ * 3 * DIM];
__device__ f16 g_ah [(size_t)BATCH * SEQ * DIM];

// ---------------------------------------------------------------------------
// helpers
// ---------------------------------------------------------------------------
__device__ __forceinline__ uint32_t smem_u32(const void* p) {
    uint32_t a;
    asm("{ .reg .u64 t; cvta.to.shared.u64 t, %1; cvt.u32.u64 %0, t; }" : "=r"(a) : "l"(p));
    return a;
}

__device__ __forceinline__ void ldmatrix_x4(uint32_t* r, uint32_t addr) {
    asm volatile("ldmatrix.sync.aligned.m8n8.x4.shared.b16 {%0,%1,%2,%3}, [%4];"
                 : "=r"(r[0]), "=r"(r[1]), "=r"(r[2]), "=r"(r[3]) : "r"(addr));
}

__device__ __forceinline__ void ldmatrix_x4_trans(uint32_t* r, uint32_t addr) {
    asm volatile("ldmatrix.sync.aligned.m8n8.x4.trans.shared.b16 {%0,%1,%2,%3}, [%4];"
                 : "=r"(r[0]), "=r"(r[1]), "=r"(r[2]), "=r"(r[3]) : "r"(addr));
}

__device__ __forceinline__ void mma_f16(float* c, const uint32_t* a, const uint32_t* b) {
    asm volatile(
        "mma.sync.aligned.m16n8k16.row.col.f32.f16.f16.f32 "
        "{%0,%1,%2,%3}, {%4,%5,%6,%7}, {%8,%9}, {%0,%1,%2,%3};"
        : "+f"(c[0]), "+f"(c[1]), "+f"(c[2]), "+f"(c[3])
        : "r"(a[0]), "r"(a[1]), "r"(a[2]), "r"(a[3]), "r"(b[0]), "r"(b[1]));
}

__device__ __forceinline__ uint32_t pack_f16(float a, float b) {
    __half2 t = __floats2half2_rn(a, b);
    return *(uint32_t*)&t;
}

__device__ __forceinline__ void cp16(uint32_t dst, const void* src) {
    asm volatile("cp.async.cg.shared.global [%0], [%1], 16;" :: "r"(dst), "l"(src));
}
#define CP_COMMIT() asm volatile("cp.async.commit_group;" ::: "memory")
#define CP_WAIT1()  asm volatile("cp.async.wait_group 1;" ::: "memory")
#define CP_WAIT0()  asm volatile("cp.async.wait_group 0;" ::: "memory")

// ---------------------------------------------------------------------------
// fp32 -> fp16 converters
// ---------------------------------------------------------------------------
__global__ void cvt_hi(const float4* __restrict__ in, uint2* __restrict__ hi, int n4)
{
    int i = blockIdx.x * blockDim.x + threadIdx.x;
    if (i >= n4) return;
    float4 f = in[i];
    hi[i] = make_uint2(pack_f16(f.x, f.y), pack_f16(f.z, f.w));
}

__global__ void cvt_hilo(const float4* __restrict__ in,
                         uint2* __restrict__ hi, uint2* __restrict__ lo, int n4)
{
    int i = blockIdx.x * blockDim.x + threadIdx.x;
    if (i >= n4) return;
    float4 f = in[i];
    float v[4] = {f.x, f.y, f.z, f.w};
    float h[4];
#pragma unroll
    for (int j = 0; j < 4; j++) h[j] = __half2float(__float2half_rn(v[j]));
    hi[i] = make_uint2(pack_f16(h[0], h[1]), pack_f16(h[2], h[3]));
    lo[i] = make_uint2(pack_f16(v[0] - h[0], v[1] - h[1]),
                       pack_f16(v[2] - h[2], v[3] - h[3]));
}

// ---------------------------------------------------------------------------
// GEMM: 128x128 tile, fp16x2 (C = Ah*(Bh+Bl) + bias), 256 threads, 2 CTAs/SM.
// BK=32, 3-stage cp.async. Stage = [Ah | Bh | Bl] rows padded to 80B.
// OUTHALF=1: fp16 hi out, columns < qcols scaled by 0.125 (exact pow2).
// OUTHALF=0: fp32 out.
// hh/hl MMA passes split: 16 independent MMAs between dependent pairs.
// ---------------------------------------------------------------------------
#define GTILE 10240
#define GSTG  (3 * GTILE)
#define GEMM_SMEM (3 * GSTG)

template <int OUTHALF>
__global__ __launch_bounds__(256, 2)
void gemm_f16x2(int M, int N, int K,
                const f16* __restrict__ Ah,
                const f16* __restrict__ Bh, const f16* __restrict__ Bl,
                const float* __restrict__ bias, int qcols,
                float* __restrict__ C, f16* __restrict__ Ch)
{
    extern __shared__ char smem[];
    const uint32_t sb = smem_u32(smem);
    const int tid = threadIdx.x, wid = tid >> 5, lane = tid & 31;
    const int bx = blockIdx.x, by = blockIdx.y;
    const int warpM = wid & 1, warpN = wid >> 1;

    const int r = tid >> 1;
    const int cb = (tid & 1) * 2;
    const f16* pAh = Ah + (size_t)(by * 128 + r) * K;
    const f16* pBh = Bh + (size_t)(bx * 128 + r) * K;
    const f16* pBl = Bl + (size_t)(bx * 128 + r) * K;
    const uint32_t sdst = sb + (uint32_t)(r * 80 + cb * 16);

    float acc[4][4][4];
#pragma unroll
    for (int i = 0; i < 4; i++)
#pragma unroll
        for (int j = 0; j < 4; j++)
#pragma unroll
            for (int v = 0; v < 4; v++) acc[i][j][v] = 0.f;

    const int KC = K >> 5;

    auto issue = [&](int kt, int s) {
        const int k0 = kt * 32 + cb * 8;
        const uint32_t d = sdst + (uint32_t)(s * GSTG);
        cp16(d,                  pAh + k0);
        cp16(d + 16,             pAh + k0 + 8);
        cp16(d + GTILE,          pBh + k0);
        cp16(d + GTILE + 16,     pBh + k0 + 8);
        cp16(d + 2 * GTILE,      pBl + k0);
        cp16(d + 2 * GTILE + 16, pBl + k0 + 8);
        CP_COMMIT();
    };

    issue(0, 0);
    issue(1, 1);

    const int aRow = warpM * 64 + ((lane >> 3) & 1) * 8 + (lane & 7);
    const int aColHalf = (lane >> 4) * 16;
    const int bRow = warpN * 32 + (lane >> 4) * 8 + (lane & 7);
    const int bColHalf = ((lane >> 3) & 1) * 16;

    for (int kt = 0; kt < KC; kt++) {
        CP_WAIT1();
        __syncthreads();
        if (kt + 2 < KC) issue(kt + 2, (kt + 2) % 3);
        else             CP_COMMIT();

        const uint32_t sAh = sb + (uint32_t)((kt % 3) * GSTG);
        const uint32_t sBh = sAh + GTILE;
        const uint32_t sBl = sAh + 2 * GTILE;

#pragma unroll
        for (int ks = 0; ks < 2; ks++) {
            uint32_t ah[4][4], bh[4][2], bl[4][2];
            const uint32_t acol = (uint32_t)(ks * 32 + aColHalf);
            const uint32_t bcol = (uint32_t)(ks * 32 + bColHalf);
#pragma unroll
            for (int mt = 0; mt < 4; mt++) {
                uint32_t off = (uint32_t)((aRow + mt * 16) * 80) + acol;
                ldmatrix_x4(ah[mt], sAh + off);
            }
#pragma unroll
            for (int pr = 0; pr < 2; pr++) {
                uint32_t off = (uint32_t)((bRow + pr * 16) * 80) + bcol;
                uint32_t r0[4], r1[4];
                ldmatrix_x4(r0, sBh + off);
                ldmatrix_x4(r1, sBl + off);
                bh[pr * 2 + 0][0] = r0[0]; bh[pr * 2 + 0][1] = r0[1];
                bh[pr * 2 + 1][0] = r0[2]; bh[pr * 2 + 1][1] = r0[3];
                bl[pr * 2 + 0][0] = r1[0]; bl[pr * 2 + 0][1] = r1[1];
                bl[pr * 2 + 1][0] = r1[2]; bl[pr * 2 + 1][1] = r1[3];
            }
            // pass 1: all hh MMAs (16 independent)
#pragma unroll
            for (int mt = 0; mt < 4; mt++)
#pragma unroll
                for (int nt = 0; nt < 4; nt++)
                    mma_f16(acc[mt][nt], ah[mt], bh[nt]);
            // pass 2: all hl MMAs (each 16 instrs after its dependency)
#pragma unroll
            for (int mt = 0; mt < 4; mt++)
#pragma unroll
                for (int nt = 0; nt < 4; nt++)
                    mma_f16(acc[mt][nt], ah[mt], bl[nt]);
        }
    }

    const int crow = by * 128 + warpM * 64 + (lane >> 2);
    const int ccol = bx * 128 + warpN * 32 + (lane & 3) * 2;
#pragma unroll
    for (int nt = 0; nt < 4; nt++) {
        const int col = ccol + nt * 8;
        const float s = (OUTHALF && col < qcols) ? 0.125f : 1.0f;
        const float b0 = bias[col], b1 = bias[col + 1];
#pragma unroll
        for (int mt = 0; mt < 4; mt++) {
            const int r0 = crow + mt * 16;
            const float v00 = (acc[mt][nt][0] + b0) * s, v01 = (acc[mt][nt][1] + b1) * s;
            const float v10 = (acc[mt][nt][2] + b0) * s, v11 = (acc[mt][nt][3] + b1) * s;
            if (OUTHALF) {
                *(uint32_t*)(Ch + (size_t)r0 * N + col)       = pack_f16(v00, v01);
                *(uint32_t*)(Ch + (size_t)(r0 + 8) * N + col) = pack_f16(v10, v11);
            } else {
                *(float2*)(C + (size_t)r0 * N + col)       = make_float2(v00, v01);
                *(float2*)(C + (size_t)(r0 + 8) * N + col) = make_float2(v10, v11);
            }
        }
    }
}

// ---------------------------------------------------------------------------
// Flash attention, pure fp16 mma.sync, causal. Q pre-scaled by 0.125 upstream.
// Grid: (SEQ/128, B*H), 256 threads, 2 CTAs/SM. 3-stage cp.async.
// Stage (18432B) = [Kh 9216 | Vh 9216], rows padded to 144B.
// ---------------------------------------------------------------------------
#define ASTR 144
#define KV_T 9216
#define STG_A 18432
#define ATT_SMEM (3 * STG_A)       // 55296

__global__ __launch_bounds__(256, 2)
void attn_mma(const f16* __restrict__ qkvh, f16* __restrict__ oh,
              const int* __restrict__ maskp)
{
    extern __shared__ char sm[];
    const uint32_t sb = smem_u32(sm);
    const int tid = threadIdx.x, wid = tid >> 5, lane = tid & 31;
    const int qt = gridDim.x - 1 - blockIdx.x;     // long CTAs first
    const int bh = blockIdx.y;
    const int b = bh >> 4, h = bh & 15;
    const int mask = maskp[0];
    const int q0 = qt * 128;

    // ---- stage Qh via cp.async, consume into registers ----
    {
        const int r = tid >> 1, c0 = (tid & 1) * 4;
        const size_t grow = ((size_t)(b * SEQ + q0 + r)) * (3 * DIM) + h * 64 + c0 * 8;
        const uint32_t dh = sb + (uint32_t)(r * ASTR + c0 * 16);
#pragma unroll
        for (int j = 0; j < 4; j++)
            cp16(dh + j * 16, qkvh + grow + j * 8);
        CP_COMMIT();
        CP_WAIT0();
        __syncthreads();
    }

    uint32_t qh[4][4];
#pragma unroll
    for (int j = 0; j < 4; j++) {
        uint32_t addr = sb + (uint32_t)((wid * 16 + (lane & 15)) * ASTR
                       + (j * 16 + ((lane >> 4) & 1) * 8) * 2);
        ldmatrix_x4(qh[j], addr);
    }
    __syncthreads();

    float o[8][4];
#pragma unroll
    for (int t = 0; t < 8; t++)
#pragma unroll
        for (int v = 0; v < 4; v++) o[t][v] = 0.f;
    float m0 = -1e30f, m1 = -1e30f, l0 = 0.f, l1 = 0.f;

    const int nkt_load = mask ? (2 * qt + 2) : (SEQ / 64);
    const int nkt_w    = mask ? (2 * qt + 1 + (wid >= 4 ? 1 : 0)) : (SEQ / 64);

    // K/V issue: threads 0-127 -> K rows, 128-255 -> V rows (hi only)
    const int tt = tid & 127;
    const int kr = tt >> 1, kc0 = (tt & 1) * 4;
    const size_t kvcol = h * 64 + (tid < 128 ? DIM : 2 * DIM) + kc0 * 8;
    const uint32_t kvdst = (uint32_t)((tid < 128 ? 0 : KV_T) + kr * ASTR + kc0 * 16);
    auto issueKV = [&](int kt, int s) {
        const size_t grow = ((size_t)(b * SEQ + kt * 64 + kr)) * (3 * DIM) + kvcol;
        const uint32_t d = sb + (uint32_t)(s * STG_A) + kvdst;
#pragma unroll
        for (int j = 0; j < 4; j++)
            cp16(d + j * 16, qkvh + grow + j * 8);
        CP_COMMIT();
    };

    issueKV(0, 0);
    if (nkt_load > 1) issueKV(1, 1); else CP_COMMIT();

    const uint32_t koff = (uint32_t)(
        (((lane >> 4) << 3) + (lane & 7)) * ASTR + (((lane >> 3) & 1) * 8) * 2);
    const uint32_t voff = (uint32_t)(KV_T +
        ((((lane >> 3) & 1) * 8 + (lane & 7)) * ASTR) + (((lane >> 4) & 1) * 8) * 2);

    for (int kt = 0; kt < nkt_load; kt++) {
        CP_WAIT1();
        __syncthreads();
        if (kt + 2 < nkt_load) issueKV(kt + 2, (kt + 2) % 3);
        else                   CP_COMMIT();
        if (kt >= nkt_w) continue;

        const uint32_t stg = sb + (uint32_t)((kt % 3) * STG_A);
        const uint32_t kfrag = stg + koff;
        const uint32_t vfrag = stg + voff;

        // ---- scores = Qs * Kh ----
        float sc[8][4];
#pragma unroll
        for (int t = 0; t < 8; t++)
#pragma unroll
            for (int v = 0; v < 4; v++) sc[t][v] = 0.f;

#pragma unroll
        for (int j = 0; j < 4; j++) {
#pragma unroll
            for (int t = 0; t < 4; t++) {
                uint32_t addr = kfrag + (uint32_t)(t * 16 * ASTR + j * 32);
                uint32_t rh[4];
                ldmatrix_x4(rh, addr);
                mma_f16(sc[2 * t + 0], qh[j], rh);
                mma_f16(sc[2 * t + 1], qh[j], rh + 2);
            }
        }

        // ---- online softmax ----
        const int row0 = q0 + wid * 16 + (lane >> 2);
        const int row1 = row0 + 8;
        const int cbase = kt * 64 + (lane & 3) * 2;
        const bool needmask = mask && (kt * 64 + 63 > q0 + wid * 16);
        if (needmask) {
#pragma unroll
            for (int t = 0; t < 8; t++) {
                int c0 = cbase + t * 8, c1 = c0 + 1;
                if (c0 > row0) sc[t][0] = -1e30f;
                if (c1 > row0) sc[t][1] = -1e30f;
                if (c0 > row1) sc[t][2] = -1e30f;
                if (c1 > row1) sc[t][3] = -1e30f;
            }
        }
        float mt0 = -1e30f, mt1 = -1e30f;
#pragma unroll
        for (int t = 0; t < 8; t++) {
            mt0 = fmaxf(mt0, fmaxf(sc[t][0], sc[t][1]));
            mt1 = fmaxf(mt1, fmaxf(sc[t][2], sc[t][3]));
        }
        mt0 = fmaxf(mt0, __shfl_xor_sync(0xffffffffu, mt0, 1));
        mt0 = fmaxf(mt0, __shfl_xor_sync(0xffffffffu, mt0, 2));
        mt1 = fmaxf(mt1, __shfl_xor_sync(0xffffffffu, mt1, 1));
        mt1 = fmaxf(mt1, __shfl_xor_sync(0xffffffffu, mt1, 2));
        const float mn0 = fmaxf(m0, mt0), mn1 = fmaxf(m1, mt1);
        const float a0 = __expf(m0 - mn0), a1 = __expf(m1 - mn1);

        uint32_t ph[8][2];
        float s0 = 0.f, s1 = 0.f;
#pragma unroll
        for (int t = 0; t < 8; t++) {
            float p00 = __expf(sc[t][0] - mn0);
            float p01 = __expf(sc[t][1] - mn0);
            float p10 = __expf(sc[t][2] - mn1);
            float p11 = __expf(sc[t][3] - mn1);
            s0 += p00 + p01;
            s1 += p10 + p11;
            ph[t][0] = pack_f16(p00, p01);
            ph[t][1] = pack_f16(p10, p11);
        }
        s0 += __shfl_xor_sync(0xffffffffu, s0, 1);
        s0 += __shfl_xor_sync(0xffffffffu, s0, 2);
        s1 += __shfl_xor_sync(0xffffffffu, s1, 1);
        s1 += __shfl_xor_sync(0xffffffffu, s1, 2);
        m0 = mn0; m1 = mn1;
        l0 = l0 * a0 + s0;
        l1 = l1 * a1 + s1;
#pragma unroll
        for (int t = 0; t < 8; t++) {
            o[t][0] *= a0; o[t][1] *= a0;
            o[t][2] *= a1; o[t][3] *= a1;
        }

        // ---- O += Ph * Vh ----
#pragma unroll
        for (int j = 0; j < 4; j++) {
            uint32_t afh[4] = { ph[2*j][0], ph[2*j][1], ph[2*j+1][0], ph[2*j+1][1] };
#pragma unroll
            for (int t = 0; t < 4; t++) {
                uint32_t addr = vfrag + (uint32_t)(j * 16 * ASTR + t * 32);
                uint32_t rh[4];
                ldmatrix_x4_trans(rh, addr);
                mma_f16(o[2 * t + 0], afh, rh);
                mma_f16(o[2 * t + 1], afh, rh + 2);
            }
        }
    }

    // ---- write O (fp16 hi — feeds proj as A operand) ----
    const float il0 = 1.0f / l0, il1 = 1.0f / l1;
    const int orow = q0 + wid * 16 + (lane >> 2);
    const size_t obase = ((size_t)b * SEQ + orow) * DIM + h * 64 + (lane & 3) * 2;
#pragma unroll
    for (int t = 0; t < 8; t++) {
        *(uint32_t*)(oh + obase + t * 8)           = pack_f16(o[t][0] * il0, o[t][1] * il0);
        *(uint32_t*)(oh + obase + 8 * DIM + t * 8) = pack_f16(o[t][2] * il1, o[t][3] * il1);
    }
}

// ---------------------------------------------------------------------------
// Launch
// ---------------------------------------------------------------------------
extern "C" void kernel_launch(void* const* d_in, const int* in_sizes, int n_in,
                              void* d_out, int out_size)
{
    const float* x     = (const float*)d_in[0];
    const float* w_in  = (const float*)d_in[1];
    const float* b_in  = (const float*)d_in[2];
    const float* w_out = (const float*)d_in[3];
    const float* b_out = (const float*)d_in[4];
    const int*   mask  = (const int*)d_in[5];
    float* out = (float*)d_out;

    f16 *xh, *wih, *wil, *woh, *wol, *qkvh, *ah;
    cudaGetSymbolAddress((void**)&xh,  g_xh);
    cudaGetSymbolAddress((void**)&wih, g_wih);
    cudaGetSymbolAddress((void**)&wil, g_wil);
    cudaGetSymbolAddress((void**)&woh, g_woh);
    cudaGetSymbolAddress((void**)&wol, g_wol);
    cudaGetSymbolAddress((void**)&qkvh, g_qkvh);
    cudaGetSymbolAddress((void**)&ah,  g_ah);

    const int M = BATCH * SEQ;      // 4096
    const int K = DIM;              // 1024
    const int N1 = 3 * DIM;         // 3072
    const int N2 = DIM;             // 1024

    cudaFuncSetAttribute(gemm_f16x2<0>, cudaFuncAttributeMaxDynamicSharedMemorySize, GEMM_SMEM);
    cudaFuncSetAttribute(gemm_f16x2<1>, cudaFuncAttributeMaxDynamicSharedMemorySize, GEMM_SMEM);
    cudaFuncSetAttribute(attn_mma,      cudaFuncAttributeMaxDynamicSharedMemorySize, ATT_SMEM);

    // 0) convert inputs (x: hi only; weights: hi+lo)
    {
        int n4x = M * K / 4;
        int n4w = N1 * K / 4;
        int n4o = N2 * K / 4;
        cvt_hi  <<<(n4x + 255) / 256, 256>>>((const float4*)x, (uint2*)xh, n4x);
        cvt_hilo<<<(n4w + 255) / 256, 256>>>((const float4*)w_in, (uint2*)wih, (uint2*)wil, n4w);
        cvt_hilo<<<(n4o + 255) / 256, 256>>>((const float4*)w_out, (uint2*)woh, (uint2*)wol, n4o);
    }
    // 1) QKV projection -> fp16 hi (Q columns pre-scaled by 0.125)
    {
        dim3 grid(N1 / 128, M / 128);
        gemm_f16x2<1><<<grid, 256, GEMM_SMEM>>>(M, N1, K, xh, wih, wil, b_in, DIM,
                                                nullptr, qkvh);
    }
    // 2) causal attention (pure fp16 K/V) -> fp16 hi
    {
        dim3 grid(SEQ / 128, BATCH * HEADS);
        attn_mma<<<grid, 256, ATT_SMEM>>>(qkvh, ah, mask);
    }
    // 3) output projection -> fp32 out
    {
        dim3 grid(N2 / 128, M / 128);
        gemm_f16x2<0><<<grid, 256, GEMM_SMEM>>>(M, N2, K, ah, woh, wol, b_out, 0,
                                                out, nullptr);
    }
}

// round 10
// speedup vs baseline: 1.6095x; 1.2848x over previous
#include <cuda_runtime.h>
#include <cuda_fp16.h>
#include <cstdint>

// Problem constants
#define BATCH 2
#define SEQ   2048
#define DIM   1024
#define HEADS 16
#define DHEAD 64

typedef __half f16;

// Scratch (device globals — no allocations allowed)
__device__ f16 g_xh [(size_t)BATCH * SEQ * DIM];
__device__ f16 g_wih[(size_t)3 * DIM * DIM];
__device__ f16 g_woh[(size_t)DIM * DIM];
__device__ f16 g_wol[(size_t)DIM * DIM];
__device__ f16 g_qkvh[(size_t)BATCH * SEQ * 3 * DIM];
__device__ f16 g_ah [(size_t)BATCH * SEQ * DIM];

// ---------------------------------------------------------------------------
// helpers
// ---------------------------------------------------------------------------
__device__ __forceinline__ uint32_t smem_u32(const void* p) {
    uint32_t a;
    asm("{ .reg .u64 t; cvta.to.shared.u64 t, %1; cvt.u32.u64 %0, t; }" : "=r"(a) : "l"(p));
    return a;
}

__device__ __forceinline__ void ldmatrix_x4(uint32_t* r, uint32_t addr) {
    asm volatile("ldmatrix.sync.aligned.m8n8.x4.shared.b16 {%0,%1,%2,%3}, [%4];"
                 : "=r"(r[0]), "=r"(r[1]), "=r"(r[2]), "=r"(r[3]) : "r"(addr));
}

__device__ __forceinline__ void ldmatrix_x4_trans(uint32_t* r, uint32_t addr) {
    asm volatile("ldmatrix.sync.aligned.m8n8.x4.trans.shared.b16 {%0,%1,%2,%3}, [%4];"
                 : "=r"(r[0]), "=r"(r[1]), "=r"(r[2]), "=r"(r[3]) : "r"(addr));
}

__device__ __forceinline__ void mma_f16(float* c, const uint32_t* a, const uint32_t* b) {
    asm volatile(
        "mma.sync.aligned.m16n8k16.row.col.f32.f16.f16.f32 "
        "{%0,%1,%2,%3}, {%4,%5,%6,%7}, {%8,%9}, {%0,%1,%2,%3};"
        : "+f"(c[0]), "+f"(c[1]), "+f"(c[2]), "+f"(c[3])
        : "r"(a[0]), "r"(a[1]), "r"(a[2]), "r"(a[3]), "r"(b[0]), "r"(b[1]));
}

__device__ __forceinline__ uint32_t pack_f16(float a, float b) {
    __half2 t = __floats2half2_rn(a, b);
    return *(uint32_t*)&t;
}

__device__ __forceinline__ void cp16(uint32_t dst, const void* src) {
    asm volatile("cp.async.cg.shared.global [%0], [%1], 16;" :: "r"(dst), "l"(src));
}
#define CP_COMMIT() asm volatile("cp.async.commit_group;" ::: "memory")
#define CP_WAIT1()  asm volatile("cp.async.wait_group 1;" ::: "memory")
#define CP_WAIT0()  asm volatile("cp.async.wait_group 0;" ::: "memory")

// ---------------------------------------------------------------------------
// fused fp32 -> fp16 conversion for x (hi), w_in (hi), w_out (hi+lo)
// ---------------------------------------------------------------------------
#define N4X (BATCH * SEQ * DIM / 4)      // 1048576
#define N4W (3 * DIM * DIM / 4)          // 786432
#define N4O (DIM * DIM / 4)              // 262144

__global__ void cvt_all(const float4* __restrict__ x,
                        const float4* __restrict__ w_in,
                        const float4* __restrict__ w_out,
                        uint2* __restrict__ xh, uint2* __restrict__ wih,
                        uint2* __restrict__ woh, uint2* __restrict__ wol)
{
    int i = blockIdx.x * blockDim.x + threadIdx.x;
    if (i < N4X) {
        float4 f = x[i];
        xh[i] = make_uint2(pack_f16(f.x, f.y), pack_f16(f.z, f.w));
    }
    if (i < N4W) {
        float4 f = w_in[i];
        wih[i] = make_uint2(pack_f16(f.x, f.y), pack_f16(f.z, f.w));
    }
    if (i < N4O) {
        float4 f = w_out[i];
        float v[4] = {f.x, f.y, f.z, f.w};
        float h[4];
#pragma unroll
        for (int j = 0; j < 4; j++) h[j] = __half2float(__float2half_rn(v[j]));
        woh[i] = make_uint2(pack_f16(h[0], h[1]), pack_f16(h[2], h[3]));
        wol[i] = make_uint2(pack_f16(v[0] - h[0], v[1] - h[1]),
                            pack_f16(v[2] - h[2], v[3] - h[3]));
    }
}

// ---------------------------------------------------------------------------
// GEMM: 128x128 tile, 256 threads, 2 CTAs/SM, BK=32, 3-stage cp.async.
// USELO=1: C = Ah*(Bh+Bl) + bias (fp16x2). USELO=0: C = Ah*Bh + bias.
// OUTHALF=1: fp16 out, columns < qcols scaled 0.125. OUTHALF=0: fp32 out.
// Stage = [Ah | Bh (| Bl)] rows padded to 80B.
// ---------------------------------------------------------------------------
#define GTILE 10240

template <int OUTHALF, int USELO>
__global__ __launch_bounds__(256, 2)
void gemm_k(int M, int N, int K,
            const f16* __restrict__ Ah,
            const f16* __restrict__ Bh, const f16* __restrict__ Bl,
            const float* __restrict__ bias, int qcols,
            float* __restrict__ C, f16* __restrict__ Ch)
{
    constexpr uint32_t STG = (USELO ? 3 : 2) * GTILE;
    extern __shared__ char smem[];
    const uint32_t sb = smem_u32(smem);
    const int tid = threadIdx.x, wid = tid >> 5, lane = tid & 31;
    const int bx = blockIdx.x, by = blockIdx.y;
    const int warpM = wid & 1, warpN = wid >> 1;

    const int r = tid >> 1;
    const int cb = (tid & 1) * 2;
    const f16* pAh = Ah + (size_t)(by * 128 + r) * K;
    const f16* pBh = Bh + (size_t)(bx * 128 + r) * K;
    const f16* pBl = USELO ? (Bl + (size_t)(bx * 128 + r) * K) : nullptr;
    const uint32_t sdst = sb + (uint32_t)(r * 80 + cb * 16);

    float acc[4][4][4];
#pragma unroll
    for (int i = 0; i < 4; i++)
#pragma unroll
        for (int j = 0; j < 4; j++)
#pragma unroll
            for (int v = 0; v < 4; v++) acc[i][j][v] = 0.f;

    const int KC = K >> 5;

    auto issue = [&](int kt, int s) {
        const int k0 = kt * 32 + cb * 8;
        const uint32_t d = sdst + (uint32_t)(s * STG);
        cp16(d,              pAh + k0);
        cp16(d + 16,         pAh + k0 + 8);
        cp16(d + GTILE,      pBh + k0);
        cp16(d + GTILE + 16, pBh + k0 + 8);
        if (USELO) {
            cp16(d + 2 * GTILE,      pBl + k0);
            cp16(d + 2 * GTILE + 16, pBl + k0 + 8);
        }
        CP_COMMIT();
    };

    issue(0, 0);
    issue(1, 1);

    const int aRow = warpM * 64 + ((lane >> 3) & 1) * 8 + (lane & 7);
    const int aColHalf = (lane >> 4) * 16;
    const int bRow = warpN * 32 + (lane >> 4) * 8 + (lane & 7);
    const int bColHalf = ((lane >> 3) & 1) * 16;

    for (int kt = 0; kt < KC; kt++) {
        CP_WAIT1();
        __syncthreads();
        if (kt + 2 < KC) issue(kt + 2, (kt + 2) % 3);
        else             CP_COMMIT();

        const uint32_t sAh = sb + (uint32_t)((kt % 3) * STG);
        const uint32_t sBh = sAh + GTILE;
        const uint32_t sBl = sAh + 2 * GTILE;

#pragma unroll
        for (int ks = 0; ks < 2; ks++) {
            uint32_t ah[4][4], bh[4][2], bl[4][2];
            const uint32_t acol = (uint32_t)(ks * 32 + aColHalf);
            const uint32_t bcol = (uint32_t)(ks * 32 + bColHalf);
#pragma unroll
            for (int mt = 0; mt < 4; mt++) {
                uint32_t off = (uint32_t)((aRow + mt * 16) * 80) + acol;
                ldmatrix_x4(ah[mt], sAh + off);
            }
#pragma unroll
            for (int pr = 0; pr < 2; pr++) {
                uint32_t off = (uint32_t)((bRow + pr * 16) * 80) + bcol;
                uint32_t r0[4];
                ldmatrix_x4(r0, sBh + off);
                bh[pr * 2 + 0][0] = r0[0]; bh[pr * 2 + 0][1] = r0[1];
                bh[pr * 2 + 1][0] = r0[2]; bh[pr * 2 + 1][1] = r0[3];
                if (USELO) {
                    uint32_t r1[4];
                    ldmatrix_x4(r1, sBl + off);
                    bl[pr * 2 + 0][0] = r1[0]; bl[pr * 2 + 0][1] = r1[1];
                    bl[pr * 2 + 1][0] = r1[2]; bl[pr * 2 + 1][1] = r1[3];
                }
            }
#pragma unroll
            for (int mt = 0; mt < 4; mt++)
#pragma unroll
                for (int nt = 0; nt < 4; nt++)
                    mma_f16(acc[mt][nt], ah[mt], bh[nt]);
            if (USELO) {
#pragma unroll
                for (int mt = 0; mt < 4; mt++)
#pragma unroll
                    for (int nt = 0; nt < 4; nt++)
                        mma_f16(acc[mt][nt], ah[mt], bl[nt]);
            }
        }
    }

    const int crow = by * 128 + warpM * 64 + (lane >> 2);
    const int ccol = bx * 128 + warpN * 32 + (lane & 3) * 2;
#pragma unroll
    for (int nt = 0; nt < 4; nt++) {
        const int col = ccol + nt * 8;
        const float s = (OUTHALF && col < qcols) ? 0.125f : 1.0f;
        const float b0 = bias[col], b1 = bias[col + 1];
#pragma unroll
        for (int mt = 0; mt < 4; mt++) {
            const int r0 = crow + mt * 16;
            const float v00 = (acc[mt][nt][0] + b0) * s, v01 = (acc[mt][nt][1] + b1) * s;
            const float v10 = (acc[mt][nt][2] + b0) * s, v11 = (acc[mt][nt][3] + b1) * s;
            if (OUTHALF) {
                *(uint32_t*)(Ch + (size_t)r0 * N + col)       = pack_f16(v00, v01);
                *(uint32_t*)(Ch + (size_t)(r0 + 8) * N + col) = pack_f16(v10, v11);
            } else {
                *(float2*)(C + (size_t)r0 * N + col)       = make_float2(v00, v01);
                *(float2*)(C + (size_t)(r0 + 8) * N + col) = make_float2(v10, v11);
            }
        }
    }
}

// ---------------------------------------------------------------------------
// Flash attention, pure fp16 mma.sync, causal. Q pre-scaled by 0.125.
// Grid: (SEQ/128, B*H), 256 threads, 2 CTAs/SM. 3-stage cp.async.
// Stage (18432B) = [Kh 9216 | Vh 9216], rows padded to 144B.
// ---------------------------------------------------------------------------
#define ASTR 144
#define KV_T 9216
#define STG_A 18432
#define ATT_SMEM (3 * STG_A)       // 55296

__global__ __launch_bounds__(256, 2)
void attn_mma(const f16* __restrict__ qkvh, f16* __restrict__ oh,
              const int* __restrict__ maskp)
{
    extern __shared__ char sm[];
    const uint32_t sb = smem_u32(sm);
    const int tid = threadIdx.x, wid = tid >> 5, lane = tid & 31;
    const int qt = gridDim.x - 1 - blockIdx.x;     // long CTAs first
    const int bh = blockIdx.y;
    const int b = bh >> 4, h = bh & 15;
    const int mask = maskp[0];
    const int q0 = qt * 128;

    // ---- stage Qh via cp.async, consume into registers ----
    {
        const int r = tid >> 1, c0 = (tid & 1) * 4;
        const size_t grow = ((size_t)(b * SEQ + q0 + r)) * (3 * DIM) + h * 64 + c0 * 8;
        const uint32_t dh = sb + (uint32_t)(r * ASTR + c0 * 16);
#pragma unroll
        for (int j = 0; j < 4; j++)
            cp16(dh + j * 16, qkvh + grow + j * 8);
        CP_COMMIT();
        CP_WAIT0();
        __syncthreads();
    }

    uint32_t qh[4][4];
#pragma unroll
    for (int j = 0; j < 4; j++) {
        uint32_t addr = sb + (uint32_t)((wid * 16 + (lane & 15)) * ASTR
                       + (j * 16 + ((lane >> 4) & 1) * 8) * 2);
        ldmatrix_x4(qh[j], addr);
    }
    __syncthreads();

    float o[8][4];
#pragma unroll
    for (int t = 0; t < 8; t++)
#pragma unroll
        for (int v = 0; v < 4; v++) o[t][v] = 0.f;
    float m0 = -1e30f, m1 = -1e30f, l0 = 0.f, l1 = 0.f;

    const int nkt_load = mask ? (2 * qt + 2) : (SEQ / 64);
    const int nkt_w    = mask ? (2 * qt + 1 + (wid >= 4 ? 1 : 0)) : (SEQ / 64);

    const int tt = tid & 127;
    const int kr = tt >> 1, kc0 = (tt & 1) * 4;
    const size_t kvcol = h * 64 + (tid < 128 ? DIM : 2 * DIM) + kc0 * 8;
    const uint32_t kvdst = (uint32_t)((tid < 128 ? 0 : KV_T) + kr * ASTR + kc0 * 16);
    auto issueKV = [&](int kt, int s) {
        const size_t grow = ((size_t)(b * SEQ + kt * 64 + kr)) * (3 * DIM) + kvcol;
        const uint32_t d = sb + (uint32_t)(s * STG_A) + kvdst;
#pragma unroll
        for (int j = 0; j < 4; j++)
            cp16(d + j * 16, qkvh + grow + j * 8);
        CP_COMMIT();
    };

    issueKV(0, 0);
    if (nkt_load > 1) issueKV(1, 1); else CP_COMMIT();

    const uint32_t koff = (uint32_t)(
        (((lane >> 4) << 3) + (lane & 7)) * ASTR + (((lane >> 3) & 1) * 8) * 2);
    const uint32_t voff = (uint32_t)(KV_T +
        ((((lane >> 3) & 1) * 8 + (lane & 7)) * ASTR) + (((lane >> 4) & 1) * 8) * 2);

    for (int kt = 0; kt < nkt_load; kt++) {
        CP_WAIT1();
        __syncthreads();
        if (kt + 2 < nkt_load) issueKV(kt + 2, (kt + 2) % 3);
        else                   CP_COMMIT();
        if (kt >= nkt_w) continue;

        const uint32_t stg = sb + (uint32_t)((kt % 3) * STG_A);
        const uint32_t kfrag = stg + koff;
        const uint32_t vfrag = stg + voff;

        // ---- scores = Qs * Kh ----
        float sc[8][4];
#pragma unroll
        for (int t = 0; t < 8; t++)
#pragma unroll
            for (int v = 0; v < 4; v++) sc[t][v] = 0.f;

#pragma unroll
        for (int j = 0; j < 4; j++) {
#pragma unroll
            for (int t = 0; t < 4; t++) {
                uint32_t addr = kfrag + (uint32_t)(t * 16 * ASTR + j * 32);
                uint32_t rh[4];
                ldmatrix_x4(rh, addr);
                mma_f16(sc[2 * t + 0], qh[j], rh);
                mma_f16(sc[2 * t + 1], qh[j], rh + 2);
            }
        }

        // ---- online softmax ----
        const int row0 = q0 + wid * 16 + (lane >> 2);
        const int row1 = row0 + 8;
        const int cbase = kt * 64 + (lane & 3) * 2;
        const bool needmask = mask && (kt * 64 + 63 > q0 + wid * 16);
        if (needmask) {
#pragma unroll
            for (int t = 0; t < 8; t++) {
                int c0 = cbase + t * 8, c1 = c0 + 1;
                if (c0 > row0) sc[t][0] = -1e30f;
                if (c1 > row0) sc[t][1] = -1e30f;
                if (c0 > row1) sc[t][2] = -1e30f;
                if (c1 > row1) sc[t][3] = -1e30f;
            }
        }
        float mt0 = -1e30f, mt1 = -1e30f;
#pragma unroll
        for (int t = 0; t < 8; t++) {
            mt0 = fmaxf(mt0, fmaxf(sc[t][0], sc[t][1]));
            mt1 = fmaxf(mt1, fmaxf(sc[t][2], sc[t][3]));
        }
        mt0 = fmaxf(mt0, __shfl_xor_sync(0xffffffffu, mt0, 1));
        mt0 = fmaxf(mt0, __shfl_xor_sync(0xffffffffu, mt0, 2));
        mt1 = fmaxf(mt1, __shfl_xor_sync(0xffffffffu, mt1, 1));
        mt1 = fmaxf(mt1, __shfl_xor_sync(0xffffffffu, mt1, 2));
        const float mn0 = fmaxf(m0, mt0), mn1 = fmaxf(m1, mt1);
        const float a0 = __expf(m0 - mn0), a1 = __expf(m1 - mn1);

        uint32_t ph[8][2];
        float s0 = 0.f, s1 = 0.f;
#pragma unroll
        for (int t = 0; t < 8; t++) {
            float p00 = __expf(sc[t][0] - mn0);
            float p01 = __expf(sc[t][1] - mn0);
            float p10 = __expf(sc[t][2] - mn1);
            float p11 = __expf(sc[t][3] - mn1);
            s0 += p00 + p01;
            s1 += p10 + p11;
            ph[t][0] = pack_f16(p00, p01);
            ph[t][1] = pack_f16(p10, p11);
        }
        s0 += __shfl_xor_sync(0xffffffffu, s0, 1);
        s0 += __shfl_xor_sync(0xffffffffu, s0, 2);
        s1 += __shfl_xor_sync(0xffffffffu, s1, 1);
        s1 += __shfl_xor_sync(0xffffffffu, s1, 2);
        m0 = mn0; m1 = mn1;
        l0 = l0 * a0 + s0;
        l1 = l1 * a1 + s1;
#pragma unroll
        for (int t = 0; t < 8; t++) {
            o[t][0] *= a0; o[t][1] *= a0;
            o[t][2] *= a1; o[t][3] *= a1;
        }

        // ---- O += Ph * Vh ----
#pragma unroll
        for (int j = 0; j < 4; j++) {
            uint32_t afh[4] = { ph[2*j][0], ph[2*j][1], ph[2*j+1][0], ph[2*j+1][1] };
#pragma unroll
            for (int t = 0; t < 4; t++) {
                uint32_t addr = vfrag + (uint32_t)(j * 16 * ASTR + t * 32);
                uint32_t rh[4];
                ldmatrix_x4_trans(rh, addr);
                mma_f16(o[2 * t + 0], afh, rh);
                mma_f16(o[2 * t + 1], afh, rh + 2);
            }
        }
    }

    // ---- write O (fp16 hi — feeds proj as A operand) ----
    const float il0 = 1.0f / l0, il1 = 1.0f / l1;
    const int orow = q0 + wid * 16 + (lane >> 2);
    const size_t obase = ((size_t)b * SEQ + orow) * DIM + h * 64 + (lane & 3) * 2;
#pragma unroll
    for (int t = 0; t < 8; t++) {
        *(uint32_t*)(oh + obase + t * 8)           = pack_f16(o[t][0] * il0, o[t][1] * il0);
        *(uint32_t*)(oh + obase + 8 * DIM + t * 8) = pack_f16(o[t][2] * il1, o[t][3] * il1);
    }
}

// ---------------------------------------------------------------------------
// Launch
// ---------------------------------------------------------------------------
extern "C" void kernel_launch(void* const* d_in, const int* in_sizes, int n_in,
                              void* d_out, int out_size)
{
    const float* x     = (const float*)d_in[0];
    const float* w_in  = (const float*)d_in[1];
    const float* b_in  = (const float*)d_in[2];
    const float* w_out = (const float*)d_in[3];
    const float* b_out = (const float*)d_in[4];
    const int*   mask  = (const int*)d_in[5];
    float* out = (float*)d_out;

    f16 *xh, *wih, *woh, *wol, *qkvh, *ah;
    cudaGetSymbolAddress((void**)&xh,  g_xh);
    cudaGetSymbolAddress((void**)&wih, g_wih);
    cudaGetSymbolAddress((void**)&woh, g_woh);
    cudaGetSymbolAddress((void**)&wol, g_wol);
    cudaGetSymbolAddress((void**)&qkvh, g_qkvh);
    cudaGetSymbolAddress((void**)&ah,  g_ah);

    const int M = BATCH * SEQ;      // 4096
    const int K = DIM;              // 1024
    const int N1 = 3 * DIM;         // 3072
    const int N2 = DIM;             // 1024

    const int smem_qkv  = 3 * 2 * GTILE;   // 61440 (no Bl)
    const int smem_proj = 3 * 3 * GTILE;   // 92160 (with Bl)
    cudaFuncSetAttribute((const void*)gemm_k<1,0>, cudaFuncAttributeMaxDynamicSharedMemorySize, smem_qkv);
    cudaFuncSetAttribute((const void*)gemm_k<0,1>, cudaFuncAttributeMaxDynamicSharedMemorySize, smem_proj);
    cudaFuncSetAttribute(attn_mma, cudaFuncAttributeMaxDynamicSharedMemorySize, ATT_SMEM);

    // 0) fused conversion (x hi, w_in hi, w_out hi+lo)
    cvt_all<<<(N4X + 255) / 256, 256>>>((const float4*)x, (const float4*)w_in,
                                        (const float4*)w_out,
                                        (uint2*)xh, (uint2*)wih,
                                        (uint2*)woh, (uint2*)wol);
    // 1) QKV projection (pure fp16) -> fp16 hi, Q columns pre-scaled 0.125
    {
        dim3 grid(N1 / 128, M / 128);
        gemm_k<1,0><<<grid, 256, smem_qkv>>>(M, N1, K, xh, wih, nullptr, b_in, DIM,
                                             nullptr, qkvh);
    }
    // 2) causal attention (pure fp16) -> fp16 hi
    {
        dim3 grid(SEQ / 128, BATCH * HEADS);
        attn_mma<<<grid, 256, ATT_SMEM>>>(qkvh, ah, mask);
    }
    // 3) output projection (fp16x2) -> fp32 out
    {
        dim3 grid(N2 / 128, M / 128);
        gemm_k<0,1><<<grid, 256, smem_proj>>>(M, N2, K, ah, woh, wol, b_out, 0,
                                              out, nullptr);
    }
}

// round 11
// speedup vs baseline: 1.7742x; 1.1024x over previous
#include <cuda_runtime.h>
#include <cuda_fp16.h>
#include <cstdint>

// Problem constants
#define BATCH 2
#define SEQ   2048
#define DIM   1024
#define HEADS 16
#define DHEAD 64

typedef __half f16;

// Scratch (device globals — no allocations allowed)
__device__ f16 g_xh [(size_t)BATCH * SEQ * DIM];
__device__ f16 g_wih[(size_t)3 * DIM * DIM];
__device__ f16 g_woh[(size_t)DIM * DIM];
__device__ f16 g_qkvh[(size_t)BATCH * SEQ * 3 * DIM];
__device__ f16 g_ah [(size_t)BATCH * SEQ * DIM];

// ---------------------------------------------------------------------------
// helpers
// ---------------------------------------------------------------------------
__device__ __forceinline__ uint32_t smem_u32(const void* p) {
    uint32_t a;
    asm("{ .reg .u64 t; cvta.to.shared.u64 t, %1; cvt.u32.u64 %0, t; }" : "=r"(a) : "l"(p));
    return a;
}

__device__ __forceinline__ void ldmatrix_x4(uint32_t* r, uint32_t addr) {
    asm volatile("ldmatrix.sync.aligned.m8n8.x4.shared.b16 {%0,%1,%2,%3}, [%4];"
                 : "=r"(r[0]), "=r"(r[1]), "=r"(r[2]), "=r"(r[3]) : "r"(addr));
}

__device__ __forceinline__ void ldmatrix_x4_trans(uint32_t* r, uint32_t addr) {
    asm volatile("ldmatrix.sync.aligned.m8n8.x4.trans.shared.b16 {%0,%1,%2,%3}, [%4];"
                 : "=r"(r[0]), "=r"(r[1]), "=r"(r[2]), "=r"(r[3]) : "r"(addr));
}

__device__ __forceinline__ void mma_f16(float* c, const uint32_t* a, const uint32_t* b) {
    asm volatile(
        "mma.sync.aligned.m16n8k16.row.col.f32.f16.f16.f32 "
        "{%0,%1,%2,%3}, {%4,%5,%6,%7}, {%8,%9}, {%0,%1,%2,%3};"
        : "+f"(c[0]), "+f"(c[1]), "+f"(c[2]), "+f"(c[3])
        : "r"(a[0]), "r"(a[1]), "r"(a[2]), "r"(a[3]), "r"(b[0]), "r"(b[1]));
}

__device__ __forceinline__ uint32_t pack_f16(float a, float b) {
    __half2 t = __floats2half2_rn(a, b);
    return *(uint32_t*)&t;
}

__device__ __forceinline__ void cp16(uint32_t dst, const void* src) {
    asm volatile("cp.async.cg.shared.global [%0], [%1], 16;" :: "r"(dst), "l"(src));
}
#define CP_COMMIT() asm volatile("cp.async.commit_group;" ::: "memory")
#define CP_WAIT1()  asm volatile("cp.async.wait_group 1;" ::: "memory")
#define CP_WAIT0()  asm volatile("cp.async.wait_group 0;" ::: "memory")

// ---------------------------------------------------------------------------
// fused fp32 -> fp16 conversion (all hi-only now)
// ---------------------------------------------------------------------------
#define N4X (BATCH * SEQ * DIM / 4)      // 1048576
#define N4W (3 * DIM * DIM / 4)          // 786432
#define N4O (DIM * DIM / 4)              // 262144

__global__ void cvt_all(const float4* __restrict__ x,
                        const float4* __restrict__ w_in,
                        const float4* __restrict__ w_out,
                        uint2* __restrict__ xh, uint2* __restrict__ wih,
                        uint2* __restrict__ woh)
{
    int i = blockIdx.x * blockDim.x + threadIdx.x;
    if (i < N4X) {
        float4 f = x[i];
        xh[i] = make_uint2(pack_f16(f.x, f.y), pack_f16(f.z, f.w));
    }
    if (i < N4W) {
        float4 f = w_in[i];
        wih[i] = make_uint2(pack_f16(f.x, f.y), pack_f16(f.z, f.w));
    }
    if (i < N4O) {
        float4 f = w_out[i];
        woh[i] = make_uint2(pack_f16(f.x, f.y), pack_f16(f.z, f.w));
    }
}

// ---------------------------------------------------------------------------
// GEMM: 128x128 tile, pure fp16 (C = Ah*Bh + bias), 256 threads, 2 CTAs/SM.
// BK=32, 3-stage cp.async. Stage = [Ah | Bh], rows padded to 80B.
// OUTHALF=1: fp16 out, columns < qcols scaled 0.125. OUTHALF=0: fp32 out.
// ---------------------------------------------------------------------------
#define GTILE 10240
#define GSTG  (2 * GTILE)
#define GEMM_SMEM (3 * GSTG)     // 61440

template <int OUTHALF>
__global__ __launch_bounds__(256, 2)
void gemm_k(int M, int N, int K,
            const f16* __restrict__ Ah, const f16* __restrict__ Bh,
            const float* __restrict__ bias, int qcols,
            float* __restrict__ C, f16* __restrict__ Ch)
{
    extern __shared__ char smem[];
    const uint32_t sb = smem_u32(smem);
    const int tid = threadIdx.x, wid = tid >> 5, lane = tid & 31;
    const int bx = blockIdx.x, by = blockIdx.y;
    const int warpM = wid & 1, warpN = wid >> 1;

    const int r = tid >> 1;
    const int cb = (tid & 1) * 2;
    const f16* pAh = Ah + (size_t)(by * 128 + r) * K;
    const f16* pBh = Bh + (size_t)(bx * 128 + r) * K;
    const uint32_t sdst = sb + (uint32_t)(r * 80 + cb * 16);

    float acc[4][4][4];
#pragma unroll
    for (int i = 0; i < 4; i++)
#pragma unroll
        for (int j = 0; j < 4; j++)
#pragma unroll
            for (int v = 0; v < 4; v++) acc[i][j][v] = 0.f;

    const int KC = K >> 5;

    auto issue = [&](int kt, int s) {
        const int k0 = kt * 32 + cb * 8;
        const uint32_t d = sdst + (uint32_t)(s * GSTG);
        cp16(d,              pAh + k0);
        cp16(d + 16,         pAh + k0 + 8);
        cp16(d + GTILE,      pBh + k0);
        cp16(d + GTILE + 16, pBh + k0 + 8);
        CP_COMMIT();
    };

    issue(0, 0);
    issue(1, 1);

    const int aRow = warpM * 64 + ((lane >> 3) & 1) * 8 + (lane & 7);
    const int aColHalf = (lane >> 4) * 16;
    const int bRow = warpN * 32 + (lane >> 4) * 8 + (lane & 7);
    const int bColHalf = ((lane >> 3) & 1) * 16;

    for (int kt = 0; kt < KC; kt++) {
        CP_WAIT1();
        __syncthreads();
        if (kt + 2 < KC) issue(kt + 2, (kt + 2) % 3);
        else             CP_COMMIT();

        const uint32_t sAh = sb + (uint32_t)((kt % 3) * GSTG);
        const uint32_t sBh = sAh + GTILE;

#pragma unroll
        for (int ks = 0; ks < 2; ks++) {
            uint32_t ah[4][4], bh[4][2];
            const uint32_t acol = (uint32_t)(ks * 32 + aColHalf);
            const uint32_t bcol = (uint32_t)(ks * 32 + bColHalf);
#pragma unroll
            for (int mt = 0; mt < 4; mt++) {
                uint32_t off = (uint32_t)((aRow + mt * 16) * 80) + acol;
                ldmatrix_x4(ah[mt], sAh + off);
            }
#pragma unroll
            for (int pr = 0; pr < 2; pr++) {
                uint32_t off = (uint32_t)((bRow + pr * 16) * 80) + bcol;
                uint32_t r0[4];
                ldmatrix_x4(r0, sBh + off);
                bh[pr * 2 + 0][0] = r0[0]; bh[pr * 2 + 0][1] = r0[1];
                bh[pr * 2 + 1][0] = r0[2]; bh[pr * 2 + 1][1] = r0[3];
            }
#pragma unroll
            for (int mt = 0; mt < 4; mt++)
#pragma unroll
                for (int nt = 0; nt < 4; nt++)
                    mma_f16(acc[mt][nt], ah[mt], bh[nt]);
        }
    }

    const int crow = by * 128 + warpM * 64 + (lane >> 2);
    const int ccol = bx * 128 + warpN * 32 + (lane & 3) * 2;
#pragma unroll
    for (int nt = 0; nt < 4; nt++) {
        const int col = ccol + nt * 8;
        const float s = (OUTHALF && col < qcols) ? 0.125f : 1.0f;
        const float b0 = bias[col], b1 = bias[col + 1];
#pragma unroll
        for (int mt = 0; mt < 4; mt++) {
            const int r0 = crow + mt * 16;
            const float v00 = (acc[mt][nt][0] + b0) * s, v01 = (acc[mt][nt][1] + b1) * s;
            const float v10 = (acc[mt][nt][2] + b0) * s, v11 = (acc[mt][nt][3] + b1) * s;
            if (OUTHALF) {
                *(uint32_t*)(Ch + (size_t)r0 * N + col)       = pack_f16(v00, v01);
                *(uint32_t*)(Ch + (size_t)(r0 + 8) * N + col) = pack_f16(v10, v11);
            } else {
                *(float2*)(C + (size_t)r0 * N + col)       = make_float2(v00, v01);
                *(float2*)(C + (size_t)(r0 + 8) * N + col) = make_float2(v10, v11);
            }
        }
    }
}

// ---------------------------------------------------------------------------
// Flash attention, pure fp16 mma.sync, causal. Q pre-scaled by 0.125.
// Grid: (SEQ/128, B*H), 256 threads, 2 CTAs/SM. 3-stage cp.async.
// Stage (18432B) = [Kh 9216 | Vh 9216], rows padded to 144B.
// ---------------------------------------------------------------------------
#define ASTR 144
#define KV_T 9216
#define STG_A 18432
#define ATT_SMEM (3 * STG_A)       // 55296

__global__ __launch_bounds__(256, 2)
void attn_mma(const f16* __restrict__ qkvh, f16* __restrict__ oh,
              const int* __restrict__ maskp)
{
    extern __shared__ char sm[];
    const uint32_t sb = smem_u32(sm);
    const int tid = threadIdx.x, wid = tid >> 5, lane = tid & 31;
    const int qt = gridDim.x - 1 - blockIdx.x;     // long CTAs first
    const int bh = blockIdx.y;
    const int b = bh >> 4, h = bh & 15;
    const int mask = maskp[0];
    const int q0 = qt * 128;

    // ---- stage Qh via cp.async, consume into registers ----
    {
        const int r = tid >> 1, c0 = (tid & 1) * 4;
        const size_t grow = ((size_t)(b * SEQ + q0 + r)) * (3 * DIM) + h * 64 + c0 * 8;
        const uint32_t dh = sb + (uint32_t)(r * ASTR + c0 * 16);
#pragma unroll
        for (int j = 0; j < 4; j++)
            cp16(dh + j * 16, qkvh + grow + j * 8);
        CP_COMMIT();
        CP_WAIT0();
        __syncthreads();
    }

    uint32_t qh[4][4];
#pragma unroll
    for (int j = 0; j < 4; j++) {
        uint32_t addr = sb + (uint32_t)((wid * 16 + (lane & 15)) * ASTR
                       + (j * 16 + ((lane >> 4) & 1) * 8) * 2);
        ldmatrix_x4(qh[j], addr);
    }
    __syncthreads();

    float o[8][4];
#pragma unroll
    for (int t = 0; t < 8; t++)
#pragma unroll
        for (int v = 0; v < 4; v++) o[t][v] = 0.f;
    float m0 = -1e30f, m1 = -1e30f, l0 = 0.f, l1 = 0.f;

    const int nkt_load = mask ? (2 * qt + 2) : (SEQ / 64);
    const int nkt_w    = mask ? (2 * qt + 1 + (wid >= 4 ? 1 : 0)) : (SEQ / 64);

    const int tt = tid & 127;
    const int kr = tt >> 1, kc0 = (tt & 1) * 4;
    const size_t kvcol = h * 64 + (tid < 128 ? DIM : 2 * DIM) + kc0 * 8;
    const uint32_t kvdst = (uint32_t)((tid < 128 ? 0 : KV_T) + kr * ASTR + kc0 * 16);
    auto issueKV = [&](int kt, int s) {
        const size_t grow = ((size_t)(b * SEQ + kt * 64 + kr)) * (3 * DIM) + kvcol;
        const uint32_t d = sb + (uint32_t)(s * STG_A) + kvdst;
#pragma unroll
        for (int j = 0; j < 4; j++)
            cp16(d + j * 16, qkvh + grow + j * 8);
        CP_COMMIT();
    };

    issueKV(0, 0);
    if (nkt_load > 1) issueKV(1, 1); else CP_COMMIT();

    const uint32_t koff = (uint32_t)(
        (((lane >> 4) << 3) + (lane & 7)) * ASTR + (((lane >> 3) & 1) * 8) * 2);
    const uint32_t voff = (uint32_t)(KV_T +
        ((((lane >> 3) & 1) * 8 + (lane & 7)) * ASTR) + (((lane >> 4) & 1) * 8) * 2);

    for (int kt = 0; kt < nkt_load; kt++) {
        CP_WAIT1();
        __syncthreads();
        if (kt + 2 < nkt_load) issueKV(kt + 2, (kt + 2) % 3);
        else                   CP_COMMIT();
        if (kt >= nkt_w) continue;

        const uint32_t stg = sb + (uint32_t)((kt % 3) * STG_A);
        const uint32_t kfrag = stg + koff;
        const uint32_t vfrag = stg + voff;

        // ---- scores = Qs * Kh ----
        float sc[8][4];
#pragma unroll
        for (int t = 0; t < 8; t++)
#pragma unroll
            for (int v = 0; v < 4; v++) sc[t][v] = 0.f;

#pragma unroll
        for (int j = 0; j < 4; j++) {
#pragma unroll
            for (int t = 0; t < 4; t++) {
                uint32_t addr = kfrag + (uint32_t)(t * 16 * ASTR + j * 32);
                uint32_t rh[4];
                ldmatrix_x4(rh, addr);
                mma_f16(sc[2 * t + 0], qh[j], rh);
                mma_f16(sc[2 * t + 1], qh[j], rh + 2);
            }
        }

        // ---- online softmax ----
        const int row0 = q0 + wid * 16 + (lane >> 2);
        const int row1 = row0 + 8;
        const int cbase = kt * 64 + (lane & 3) * 2;
        const bool needmask = mask && (kt * 64 + 63 > q0 + wid * 16);
        if (needmask) {
#pragma unroll
            for (int t = 0; t < 8; t++) {
                int c0 = cbase + t * 8, c1 = c0 + 1;
                if (c0 > row0) sc[t][0] = -1e30f;
                if (c1 > row0) sc[t][1] = -1e30f;
                if (c0 > row1) sc[t][2] = -1e30f;
                if (c1 > row1) sc[t][3] = -1e30f;
            }
        }
        float mt0 = -1e30f, mt1 = -1e30f;
#pragma unroll
        for (int t = 0; t < 8; t++) {
            mt0 = fmaxf(mt0, fmaxf(sc[t][0], sc[t][1]));
            mt1 = fmaxf(mt1, fmaxf(sc[t][2], sc[t][3]));
        }
        mt0 = fmaxf(mt0, __shfl_xor_sync(0xffffffffu, mt0, 1));
        mt0 = fmaxf(mt0, __shfl_xor_sync(0xffffffffu, mt0, 2));
        mt1 = fmaxf(mt1, __shfl_xor_sync(0xffffffffu, mt1, 1));
        mt1 = fmaxf(mt1, __shfl_xor_sync(0xffffffffu, mt1, 2));
        const float mn0 = fmaxf(m0, mt0), mn1 = fmaxf(m1, mt1);
        const float a0 = __expf(m0 - mn0), a1 = __expf(m1 - mn1);

        uint32_t ph[8][2];
        float s0 = 0.f, s1 = 0.f;
#pragma unroll
        for (int t = 0; t < 8; t++) {
            float p00 = __expf(sc[t][0] - mn0);
            float p01 = __expf(sc[t][1] - mn0);
            float p10 = __expf(sc[t][2] - mn1);
            float p11 = __expf(sc[t][3] - mn1);
            s0 += p00 + p01;
            s1 += p10 + p11;
            ph[t][0] = pack_f16(p00, p01);
            ph[t][1] = pack_f16(p10, p11);
        }
        s0 += __shfl_xor_sync(0xffffffffu, s0, 1);
        s0 += __shfl_xor_sync(0xffffffffu, s0, 2);
        s1 += __shfl_xor_sync(0xffffffffu, s1, 1);
        s1 += __shfl_xor_sync(0xffffffffu, s1, 2);
        m0 = mn0; m1 = mn1;
        l0 = l0 * a0 + s0;
        l1 = l1 * a1 + s1;
#pragma unroll
        for (int t = 0; t < 8; t++) {
            o[t][0] *= a0; o[t][1] *= a0;
            o[t][2] *= a1; o[t][3] *= a1;
        }

        // ---- O += Ph * Vh ----
#pragma unroll
        for (int j = 0; j < 4; j++) {
            uint32_t afh[4] = { ph[2*j][0], ph[2*j][1], ph[2*j+1][0], ph[2*j+1][1] };
#pragma unroll
            for (int t = 0; t < 4; t++) {
                uint32_t addr = vfrag + (uint32_t)(j * 16 * ASTR + t * 32);
                uint32_t rh[4];
                ldmatrix_x4_trans(rh, addr);
                mma_f16(o[2 * t + 0], afh, rh);
                mma_f16(o[2 * t + 1], afh, rh + 2);
            }
        }
    }

    // ---- write O (fp16 hi — feeds proj as A operand) ----
    const float il0 = 1.0f / l0, il1 = 1.0f / l1;
    const int orow = q0 + wid * 16 + (lane >> 2);
    const size_t obase = ((size_t)b * SEQ + orow) * DIM + h * 64 + (lane & 3) * 2;
#pragma unroll
    for (int t = 0; t < 8; t++) {
        *(uint32_t*)(oh + obase + t * 8)           = pack_f16(o[t][0] * il0, o[t][1] * il0);
        *(uint32_t*)(oh + obase + 8 * DIM + t * 8) = pack_f16(o[t][2] * il1, o[t][3] * il1);
    }
}

// ---------------------------------------------------------------------------
// Launch
// ---------------------------------------------------------------------------
extern "C" void kernel_launch(void* const* d_in, const int* in_sizes, int n_in,
                              void* d_out, int out_size)
{
    const float* x     = (const float*)d_in[0];
    const float* w_in  = (const float*)d_in[1];
    const float* b_in  = (const float*)d_in[2];
    const float* w_out = (const float*)d_in[3];
    const float* b_out = (const float*)d_in[4];
    const int*   mask  = (const int*)d_in[5];
    float* out = (float*)d_out;

    f16 *xh, *wih, *woh, *qkvh, *ah;
    cudaGetSymbolAddress((void**)&xh,  g_xh);
    cudaGetSymbolAddress((void**)&wih, g_wih);
    cudaGetSymbolAddress((void**)&woh, g_woh);
    cudaGetSymbolAddress((void**)&qkvh, g_qkvh);
    cudaGetSymbolAddress((void**)&ah,  g_ah);

    const int M = BATCH * SEQ;      // 4096
    const int K = DIM;              // 1024
    const int N1 = 3 * DIM;         // 3072
    const int N2 = DIM;             // 1024

    cudaFuncSetAttribute((const void*)gemm_k<1>, cudaFuncAttributeMaxDynamicSharedMemorySize, GEMM_SMEM);
    cudaFuncSetAttribute((const void*)gemm_k<0>, cudaFuncAttributeMaxDynamicSharedMemorySize, GEMM_SMEM);
    cudaFuncSetAttribute(attn_mma, cudaFuncAttributeMaxDynamicSharedMemorySize, ATT_SMEM);

    // 0) fused conversion (x, w_in, w_out -> fp16 hi)
    cvt_all<<<(N4X + 255) / 256, 256>>>((const float4*)x, (const float4*)w_in,
                                        (const float4*)w_out,
                                        (uint2*)xh, (uint2*)wih, (uint2*)woh);
    // 1) QKV projection (pure fp16) -> fp16, Q columns pre-scaled 0.125
    {
        dim3 grid(N1 / 128, M / 128);
        gemm_k<1><<<grid, 256, GEMM_SMEM>>>(M, N1, K, xh, wih, b_in, DIM,
                                            nullptr, qkvh);
    }
    // 2) causal attention (pure fp16) -> fp16
    {
        dim3 grid(SEQ / 128, BATCH * HEADS);
        attn_mma<<<grid, 256, ATT_SMEM>>>(qkvh, ah, mask);
    }
    // 3) output projection (pure fp16) -> fp32 out
    {
        dim3 grid(N2 / 128, M / 128);
        gemm_k<0><<<grid, 256, GEMM_SMEM>>>(M, N2, K, ah, woh, b_out, 0,
                                            out, nullptr);
    }
}

// round 12
// speedup vs baseline: 1.8994x; 1.0705x over previous
#include <cuda_runtime.h>
#include <cuda_fp16.h>
#include <cstdint>

// Problem constants
#define BATCH 2
#define SEQ   2048
#define DIM   1024
#define HEADS 16
#define DHEAD 64
#define NQT   (SEQ / 128)          // 16 q-tiles

typedef __half f16;

// Scratch (device globals — no allocations allowed)
__device__ f16 g_xh [(size_t)BATCH * SEQ * DIM];
__device__ f16 g_wih[(size_t)3 * DIM * DIM];
__device__ f16 g_woh[(size_t)DIM * DIM];
__device__ f16 g_qkvh[(size_t)BATCH * SEQ * 3 * DIM];
__device__ f16 g_ah [(size_t)BATCH * SEQ * DIM];

// ---------------------------------------------------------------------------
// helpers
// ---------------------------------------------------------------------------
__device__ __forceinline__ uint32_t smem_u32(const void* p) {
    uint32_t a;
    asm("{ .reg .u64 t; cvta.to.shared.u64 t, %1; cvt.u32.u64 %0, t; }" : "=r"(a) : "l"(p));
    return a;
}

__device__ __forceinline__ void ldmatrix_x4(uint32_t* r, uint32_t addr) {
    asm volatile("ldmatrix.sync.aligned.m8n8.x4.shared.b16 {%0,%1,%2,%3}, [%4];"
                 : "=r"(r[0]), "=r"(r[1]), "=r"(r[2]), "=r"(r[3]) : "r"(addr));
}

__device__ __forceinline__ void ldmatrix_x4_trans(uint32_t* r, uint32_t addr) {
    asm volatile("ldmatrix.sync.aligned.m8n8.x4.trans.shared.b16 {%0,%1,%2,%3}, [%4];"
                 : "=r"(r[0]), "=r"(r[1]), "=r"(r[2]), "=r"(r[3]) : "r"(addr));
}

__device__ __forceinline__ void mma_f16(float* c, const uint32_t* a, const uint32_t* b) {
    asm volatile(
        "mma.sync.aligned.m16n8k16.row.col.f32.f16.f16.f32 "
        "{%0,%1,%2,%3}, {%4,%5,%6,%7}, {%8,%9}, {%0,%1,%2,%3};"
        : "+f"(c[0]), "+f"(c[1]), "+f"(c[2]), "+f"(c[3])
        : "r"(a[0]), "r"(a[1]), "r"(a[2]), "r"(a[3]), "r"(b[0]), "r"(b[1]));
}

__device__ __forceinline__ uint32_t pack_f16(float a, float b) {
    __half2 t = __floats2half2_rn(a, b);
    return *(uint32_t*)&t;
}

__device__ __forceinline__ void cp16(uint32_t dst, const void* src) {
    asm volatile("cp.async.cg.shared.global [%0], [%1], 16;" :: "r"(dst), "l"(src));
}
#define CP_COMMIT() asm volatile("cp.async.commit_group;" ::: "memory")
#define CP_WAIT1()  asm volatile("cp.async.wait_group 1;" ::: "memory")
#define CP_WAIT0()  asm volatile("cp.async.wait_group 0;" ::: "memory")

// ---------------------------------------------------------------------------
// fused fp32 -> fp16 conversion (hi only)
// ---------------------------------------------------------------------------
#define N4X (BATCH * SEQ * DIM / 4)      // 1048576
#define N4W (3 * DIM * DIM / 4)          // 786432
#define N4O (DIM * DIM / 4)              // 262144

__global__ void cvt_all(const float4* __restrict__ x,
                        const float4* __restrict__ w_in,
                        const float4* __restrict__ w_out,
                        uint2* __restrict__ xh, uint2* __restrict__ wih,
                        uint2* __restrict__ woh)
{
    int i = blockIdx.x * blockDim.x + threadIdx.x;
    if (i < N4X) {
        float4 f = x[i];
        xh[i] = make_uint2(pack_f16(f.x, f.y), pack_f16(f.z, f.w));
    }
    if (i < N4W) {
        float4 f = w_in[i];
        wih[i] = make_uint2(pack_f16(f.x, f.y), pack_f16(f.z, f.w));
    }
    if (i < N4O) {
        float4 f = w_out[i];
        woh[i] = make_uint2(pack_f16(f.x, f.y), pack_f16(f.z, f.w));
    }
}

// ---------------------------------------------------------------------------
// GEMM: 128x128 tile, pure fp16 (C = Ah*Bh + bias), 256 threads, 2 CTAs/SM.
// BK=32, 3-stage cp.async. Stage = [Ah | Bh], rows padded to 80B.
// OUTHALF=1: fp16 out, columns < qcols scaled 0.125. OUTHALF=0: fp32 out.
// ---------------------------------------------------------------------------
#define GTILE 10240
#define GSTG  (2 * GTILE)
#define GEMM_SMEM (3 * GSTG)     // 61440

template <int OUTHALF>
__global__ __launch_bounds__(256, 2)
void gemm_k(int M, int N, int K,
            const f16* __restrict__ Ah, const f16* __restrict__ Bh,
            const float* __restrict__ bias, int qcols,
            float* __restrict__ C, f16* __restrict__ Ch)
{
    extern __shared__ char smem[];
    const uint32_t sb = smem_u32(smem);
    const int tid = threadIdx.x, wid = tid >> 5, lane = tid & 31;
    const int bx = blockIdx.x, by = blockIdx.y;
    const int warpM = wid & 1, warpN = wid >> 1;

    const int r = tid >> 1;
    const int cb = (tid & 1) * 2;
    const f16* pAh = Ah + (size_t)(by * 128 + r) * K;
    const f16* pBh = Bh + (size_t)(bx * 128 + r) * K;
    const uint32_t sdst = sb + (uint32_t)(r * 80 + cb * 16);

    float acc[4][4][4];
#pragma unroll
    for (int i = 0; i < 4; i++)
#pragma unroll
        for (int j = 0; j < 4; j++)
#pragma unroll
            for (int v = 0; v < 4; v++) acc[i][j][v] = 0.f;

    const int KC = K >> 5;

    auto issue = [&](int kt, int s) {
        const int k0 = kt * 32 + cb * 8;
        const uint32_t d = sdst + (uint32_t)(s * GSTG);
        cp16(d,              pAh + k0);
        cp16(d + 16,         pAh + k0 + 8);
        cp16(d + GTILE,      pBh + k0);
        cp16(d + GTILE + 16, pBh + k0 + 8);
        CP_COMMIT();
    };

    issue(0, 0);
    issue(1, 1);

    const int aRow = warpM * 64 + ((lane >> 3) & 1) * 8 + (lane & 7);
    const int aColHalf = (lane >> 4) * 16;
    const int bRow = warpN * 32 + (lane >> 4) * 8 + (lane & 7);
    const int bColHalf = ((lane >> 3) & 1) * 16;

    for (int kt = 0; kt < KC; kt++) {
        CP_WAIT1();
        __syncthreads();
        if (kt + 2 < KC) issue(kt + 2, (kt + 2) % 3);
        else             CP_COMMIT();

        const uint32_t sAh = sb + (uint32_t)((kt % 3) * GSTG);
        const uint32_t sBh = sAh + GTILE;

#pragma unroll
        for (int ks = 0; ks < 2; ks++) {
            uint32_t ah[4][4], bh[4][2];
            const uint32_t acol = (uint32_t)(ks * 32 + aColHalf);
            const uint32_t bcol = (uint32_t)(ks * 32 + bColHalf);
#pragma unroll
            for (int mt = 0; mt < 4; mt++) {
                uint32_t off = (uint32_t)((aRow + mt * 16) * 80) + acol;
                ldmatrix_x4(ah[mt], sAh + off);
            }
#pragma unroll
            for (int pr = 0; pr < 2; pr++) {
                uint32_t off = (uint32_t)((bRow + pr * 16) * 80) + bcol;
                uint32_t r0[4];
                ldmatrix_x4(r0, sBh + off);
                bh[pr * 2 + 0][0] = r0[0]; bh[pr * 2 + 0][1] = r0[1];
                bh[pr * 2 + 1][0] = r0[2]; bh[pr * 2 + 1][1] = r0[3];
            }
#pragma unroll
            for (int mt = 0; mt < 4; mt++)
#pragma unroll
                for (int nt = 0; nt < 4; nt++)
                    mma_f16(acc[mt][nt], ah[mt], bh[nt]);
        }
    }

    const int crow = by * 128 + warpM * 64 + (lane >> 2);
    const int ccol = bx * 128 + warpN * 32 + (lane & 3) * 2;
#pragma unroll
    for (int nt = 0; nt < 4; nt++) {
        const int col = ccol + nt * 8;
        const float s = (OUTHALF && col < qcols) ? 0.125f : 1.0f;
        const float b0 = bias[col], b1 = bias[col + 1];
#pragma unroll
        for (int mt = 0; mt < 4; mt++) {
            const int r0 = crow + mt * 16;
            const float v00 = (acc[mt][nt][0] + b0) * s, v01 = (acc[mt][nt][1] + b1) * s;
            const float v10 = (acc[mt][nt][2] + b0) * s, v11 = (acc[mt][nt][3] + b1) * s;
            if (OUTHALF) {
                *(uint32_t*)(Ch + (size_t)r0 * N + col)       = pack_f16(v00, v01);
                *(uint32_t*)(Ch + (size_t)(r0 + 8) * N + col) = pack_f16(v10, v11);
            } else {
                *(float2*)(C + (size_t)r0 * N + col)       = make_float2(v00, v01);
                *(float2*)(C + (size_t)(r0 + 8) * N + col) = make_float2(v10, v11);
            }
        }
    }
}

// ---------------------------------------------------------------------------
// Flash attention, pure fp16, causal, WORK-PAIRED: CTA bi handles q-tiles
// {bi, NQT-1-bi} -> constant 34 KV-tile loads per CTA -> one uniform wave.
// Grid: (NQT/2, B*H), 256 threads, 2 CTAs/SM. 3-stage cp.async.
// Stage (18432B) = [Kh 9216 | Vh 9216], rows padded to 144B.
// ---------------------------------------------------------------------------
#define ASTR 144
#define KV_T 9216
#define STG_A 18432
#define ATT_SMEM (3 * STG_A)       // 55296

__global__ __launch_bounds__(256, 2)
void attn_mma(const f16* __restrict__ qkvh, f16* __restrict__ oh,
              const int* __restrict__ maskp)
{
    extern __shared__ char sm[];
    const uint32_t sb = smem_u32(sm);
    const int tid = threadIdx.x, wid = tid >> 5, lane = tid & 31;
    const int bi = blockIdx.x;
    const int bh = blockIdx.y;
    const int b = bh >> 4, h = bh & 15;
    const int mask = maskp[0];

    // constant per-thread addressing
    const int tt = tid & 127;
    const int kr = tt >> 1, kc0 = (tt & 1) * 4;
    const size_t kvcol = h * 64 + (tid < 128 ? DIM : 2 * DIM) + kc0 * 8;
    const uint32_t kvdst = (uint32_t)((tid < 128 ? 0 : KV_T) + kr * ASTR + kc0 * 16);
    const uint32_t koff = (uint32_t)(
        (((lane >> 4) << 3) + (lane & 7)) * ASTR + (((lane >> 3) & 1) * 8) * 2);
    const uint32_t voff = (uint32_t)(KV_T +
        ((((lane >> 3) & 1) * 8 + (lane & 7)) * ASTR) + (((lane >> 4) & 1) * 8) * 2);

#pragma unroll 1
    for (int p = 0; p < 2; p++) {
        const int qt = p ? (NQT - 1 - bi) : bi;
        const int q0 = qt * 128;

        // ---- stage Qh via cp.async, consume into registers ----
        {
            const int r = tid >> 1, c0 = (tid & 1) * 4;
            const size_t grow = ((size_t)(b * SEQ + q0 + r)) * (3 * DIM) + h * 64 + c0 * 8;
            const uint32_t dh = sb + (uint32_t)(r * ASTR + c0 * 16);
#pragma unroll
            for (int j = 0; j < 4; j++)
                cp16(dh + j * 16, qkvh + grow + j * 8);
            CP_COMMIT();
            CP_WAIT0();
            __syncthreads();
        }

        uint32_t qh[4][4];
#pragma unroll
        for (int j = 0; j < 4; j++) {
            uint32_t addr = sb + (uint32_t)((wid * 16 + (lane & 15)) * ASTR
                           + (j * 16 + ((lane >> 4) & 1) * 8) * 2);
            ldmatrix_x4(qh[j], addr);
        }
        __syncthreads();

        float o[8][4];
#pragma unroll
        for (int t = 0; t < 8; t++)
#pragma unroll
            for (int v = 0; v < 4; v++) o[t][v] = 0.f;
        float m0 = -1e30f, m1 = -1e30f, l0 = 0.f, l1 = 0.f;

        const int nkt_load = mask ? (2 * qt + 2) : (SEQ / 64);
        const int nkt_w    = mask ? (2 * qt + 1 + (wid >= 4 ? 1 : 0)) : (SEQ / 64);

        auto issueKV = [&](int kt, int s) {
            const size_t grow = ((size_t)(b * SEQ + kt * 64 + kr)) * (3 * DIM) + kvcol;
            const uint32_t d = sb + (uint32_t)(s * STG_A) + kvdst;
#pragma unroll
            for (int j = 0; j < 4; j++)
                cp16(d + j * 16, qkvh + grow + j * 8);
            CP_COMMIT();
        };

        issueKV(0, 0);
        if (nkt_load > 1) issueKV(1, 1); else CP_COMMIT();

        for (int kt = 0; kt < nkt_load; kt++) {
            CP_WAIT1();
            __syncthreads();
            if (kt + 2 < nkt_load) issueKV(kt + 2, (kt + 2) % 3);
            else                   CP_COMMIT();
            if (kt >= nkt_w) continue;

            const uint32_t stg = sb + (uint32_t)((kt % 3) * STG_A);
            const uint32_t kfrag = stg + koff;
            const uint32_t vfrag = stg + voff;

            // ---- scores = Qs * Kh ----
            float sc[8][4];
#pragma unroll
            for (int t = 0; t < 8; t++)
#pragma unroll
                for (int v = 0; v < 4; v++) sc[t][v] = 0.f;

#pragma unroll
            for (int j = 0; j < 4; j++) {
#pragma unroll
                for (int t = 0; t < 4; t++) {
                    uint32_t addr = kfrag + (uint32_t)(t * 16 * ASTR + j * 32);
                    uint32_t rh[4];
                    ldmatrix_x4(rh, addr);
                    mma_f16(sc[2 * t + 0], qh[j], rh);
                    mma_f16(sc[2 * t + 1], qh[j], rh + 2);
                }
            }

            // ---- online softmax ----
            const int row0 = q0 + wid * 16 + (lane >> 2);
            const int row1 = row0 + 8;
            const int cbase = kt * 64 + (lane & 3) * 2;
            const bool needmask = mask && (kt * 64 + 63 > q0 + wid * 16);
            if (needmask) {
#pragma unroll
                for (int t = 0; t < 8; t++) {
                    int c0 = cbase + t * 8, c1 = c0 + 1;
                    if (c0 > row0) sc[t][0] = -1e30f;
                    if (c1 > row0) sc[t][1] = -1e30f;
                    if (c0 > row1) sc[t][2] = -1e30f;
                    if (c1 > row1) sc[t][3] = -1e30f;
                }
            }
            float mt0 = -1e30f, mt1 = -1e30f;
#pragma unroll
            for (int t = 0; t < 8; t++) {
                mt0 = fmaxf(mt0, fmaxf(sc[t][0], sc[t][1]));
                mt1 = fmaxf(mt1, fmaxf(sc[t][2], sc[t][3]));
            }
            mt0 = fmaxf(mt0, __shfl_xor_sync(0xffffffffu, mt0, 1));
            mt0 = fmaxf(mt0, __shfl_xor_sync(0xffffffffu, mt0, 2));
            mt1 = fmaxf(mt1, __shfl_xor_sync(0xffffffffu, mt1, 1));
            mt1 = fmaxf(mt1, __shfl_xor_sync(0xffffffffu, mt1, 2));
            const float mn0 = fmaxf(m0, mt0), mn1 = fmaxf(m1, mt1);
            const float a0 = __expf(m0 - mn0), a1 = __expf(m1 - mn1);

            uint32_t ph[8][2];
            float s0 = 0.f, s1 = 0.f;
#pragma unroll
            for (int t = 0; t < 8; t++) {
                float p00 = __expf(sc[t][0] - mn0);
                float p01 = __expf(sc[t][1] - mn0);
                float p10 = __expf(sc[t][2] - mn1);
                float p11 = __expf(sc[t][3] - mn1);
                s0 += p00 + p01;
                s1 += p10 + p11;
                ph[t][0] = pack_f16(p00, p01);
                ph[t][1] = pack_f16(p10, p11);
            }
            s0 += __shfl_xor_sync(0xffffffffu, s0, 1);
            s0 += __shfl_xor_sync(0xffffffffu, s0, 2);
            s1 += __shfl_xor_sync(0xffffffffu, s1, 1);
            s1 += __shfl_xor_sync(0xffffffffu, s1, 2);
            m0 = mn0; m1 = mn1;
            l0 = l0 * a0 + s0;
            l1 = l1 * a1 + s1;
#pragma unroll
            for (int t = 0; t < 8; t++) {
                o[t][0] *= a0; o[t][1] *= a0;
                o[t][2] *= a1; o[t][3] *= a1;
            }

            // ---- O += Ph * Vh ----
#pragma unroll
            for (int j = 0; j < 4; j++) {
                uint32_t afh[4] = { ph[2*j][0], ph[2*j][1], ph[2*j+1][0], ph[2*j+1][1] };
#pragma unroll
                for (int t = 0; t < 4; t++) {
                    uint32_t addr = vfrag + (uint32_t)(j * 16 * ASTR + t * 32);
                    uint32_t rh[4];
                    ldmatrix_x4_trans(rh, addr);
                    mma_f16(o[2 * t + 0], afh, rh);
                    mma_f16(o[2 * t + 1], afh, rh + 2);
                }
            }
        }

        // ---- write O (fp16 — feeds proj as A operand) ----
        const float il0 = 1.0f / l0, il1 = 1.0f / l1;
        const int orow = q0 + wid * 16 + (lane >> 2);
        const size_t obase = ((size_t)b * SEQ + orow) * DIM + h * 64 + (lane & 3) * 2;
#pragma unroll
        for (int t = 0; t < 8; t++) {
            *(uint32_t*)(oh + obase + t * 8)           = pack_f16(o[t][0] * il0, o[t][1] * il0);
            *(uint32_t*)(oh + obase + 8 * DIM + t * 8) = pack_f16(o[t][2] * il1, o[t][3] * il1);
        }

        // drain outstanding cp.async before reusing smem for next sub-tile
        CP_WAIT0();
        __syncthreads();
    }
}

// ---------------------------------------------------------------------------
// Launch
// ---------------------------------------------------------------------------
extern "C" void kernel_launch(void* const* d_in, const int* in_sizes, int n_in,
                              void* d_out, int out_size)
{
    const float* x     = (const float*)d_in[0];
    const float* w_in  = (const float*)d_in[1];
    const float* b_in  = (const float*)d_in[2];
    const float* w_out = (const float*)d_in[3];
    const float* b_out = (const float*)d_in[4];
    const int*   mask  = (const int*)d_in[5];
    float* out = (float*)d_out;

    f16 *xh, *wih, *woh, *qkvh, *ah;
    cudaGetSymbolAddress((void**)&xh,  g_xh);
    cudaGetSymbolAddress((void**)&wih, g_wih);
    cudaGetSymbolAddress((void**)&woh, g_woh);
    cudaGetSymbolAddress((void**)&qkvh, g_qkvh);
    cudaGetSymbolAddress((void**)&ah,  g_ah);

    const int M = BATCH * SEQ;      // 4096
    const int K = DIM;              // 1024
    const int N1 = 3 * DIM;         // 3072
    const int N2 = DIM;             // 1024

    cudaFuncSetAttribute((const void*)gemm_k<1>, cudaFuncAttributeMaxDynamicSharedMemorySize, GEMM_SMEM);
    cudaFuncSetAttribute((const void*)gemm_k<0>, cudaFuncAttributeMaxDynamicSharedMemorySize, GEMM_SMEM);
    cudaFuncSetAttribute(attn_mma, cudaFuncAttributeMaxDynamicSharedMemorySize, ATT_SMEM);

    // 0) fused conversion (x, w_in, w_out -> fp16)
    cvt_all<<<(N4X + 255) / 256, 256>>>((const float4*)x, (const float4*)w_in,
                                        (const float4*)w_out,
                                        (uint2*)xh, (uint2*)wih, (uint2*)woh);
    // 1) QKV projection (pure fp16) -> fp16, Q columns pre-scaled 0.125
    {
        dim3 grid(N1 / 128, M / 128);
        gemm_k<1><<<grid, 256, GEMM_SMEM>>>(M, N1, K, xh, wih, b_in, DIM,
                                            nullptr, qkvh);
    }
    // 2) causal attention (work-paired) -> fp16
    {
        dim3 grid(NQT / 2, BATCH * HEADS);
        attn_mma<<<grid, 256, ATT_SMEM>>>(qkvh, ah, mask);
    }
    // 3) output projection (pure fp16) -> fp32 out
    {
        dim3 grid(N2 / 128, M / 128);
        gemm_k<0><<<grid, 256, GEMM_SMEM>>>(M, N2, K, ah, woh, b_out, 0,
                                            out, nullptr);
    }
}